// round 10
// baseline (speedup 1.0000x reference)
#include <cuda_runtime.h>
#include <cuda_bf16.h>
#include <math.h>
#include <stdint.h>
#include <string.h>

// Problem dims (fixed by reference)
#define Bq 2
#define Tq 2048
#define Cq 768
#define Hq 12
#define HDq 64
#define Mrows (Bq*Tq)          // 4096
#define C3 (3*Cq)              // 2304
#define C4 (4*Cq)              // 3072

// ---------------- scratch (device globals; no allocations allowed) ----------
__device__ float g_ln1[Mrows*Cq];
__device__ float g_q  [Mrows*Cq];
__device__ float g_att[Mrows*Cq];
__device__ float g_x1 [Mrows*Cq];
__device__ float g_ln2[Mrows*Cq];
__device__ float g_fc [(size_t)Mrows*C4];
__device__ __nv_bfloat16 g_kb[(size_t)Mrows*Cq];                 // K bf16 [t][h*64+d]
__device__ __nv_bfloat16 g_vT[(size_t)Bq*Hq*HDq*Tq];             // V bf16 [b,h,d][t]
// RNA-rounded weights
__device__ float g_w_attn[Cq*C3];
__device__ float g_w_ap  [Cq*Cq];
__device__ float g_w_fc  [Cq*C4];
__device__ float g_w_mp  [(size_t)C4*Cq];

// ---------------- common helpers --------------------------------------------
__device__ __forceinline__ float gelu_f(float x) {
    const float c = 0.7978845608028654f; // sqrt(2/pi)
    float t = tanhf(c * (x + 0.044715f * x * x * x));
    return 0.5f * x * (1.0f + t);
}

__device__ __forceinline__ float to_tf32(float x) {
    uint32_t r;
    asm("cvt.rna.tf32.f32 %0, %1;" : "=r"(r) : "f"(x));
    return __uint_as_float(r);
}

__device__ __forceinline__ void mma_tf32(float* c, const uint32_t* a, const uint32_t* b) {
    asm volatile(
        "mma.sync.aligned.m16n8k8.row.col.f32.tf32.tf32.f32 "
        "{%0,%1,%2,%3}, {%4,%5,%6,%7}, {%8,%9}, {%0,%1,%2,%3};\n"
        : "+f"(c[0]), "+f"(c[1]), "+f"(c[2]), "+f"(c[3])
        : "r"(a[0]), "r"(a[1]), "r"(a[2]), "r"(a[3]), "r"(b[0]), "r"(b[1]));
}

__device__ __forceinline__ void mma_bf16(float* c, const uint32_t* a, const uint32_t* b) {
    asm volatile(
        "mma.sync.aligned.m16n8k16.row.col.f32.bf16.bf16.f32 "
        "{%0,%1,%2,%3}, {%4,%5,%6,%7}, {%8,%9}, {%0,%1,%2,%3};\n"
        : "+f"(c[0]), "+f"(c[1]), "+f"(c[2]), "+f"(c[3])
        : "r"(a[0]), "r"(a[1]), "r"(a[2]), "r"(a[3]), "r"(b[0]), "r"(b[1]));
}

__device__ __forceinline__ void cpasync16(uint32_t dst, const void* src) {
    asm volatile("cp.async.cg.shared.global [%0], [%1], 16;" :: "r"(dst), "l"(src));
}

__device__ __forceinline__ uint32_t bf2u(__nv_bfloat162 h) {
    uint32_t u; memcpy(&u, &h, 4); return u;
}

// ---------------- weight rounding prep --------------------------------------
__global__ __launch_bounds__(256) void round_kernel(const float* __restrict__ in,
                                                    float* __restrict__ out, int n4)
{
    int i = blockIdx.x * 256 + threadIdx.x;
    if (i < n4) {
        float4 v = ((const float4*)in)[i];
        v.x = to_tf32(v.x); v.y = to_tf32(v.y);
        v.z = to_tf32(v.z); v.w = to_tf32(v.w);
        ((float4*)out)[i] = v;
    }
}

// ---------------- LayerNorm: one block per row (tf32-rounded output) --------
__global__ __launch_bounds__(256) void ln_kernel(const float* __restrict__ x,
                                                 const float* __restrict__ g,
                                                 const float* __restrict__ b,
                                                 float* __restrict__ o)
{
    int row = blockIdx.x;
    int tid = threadIdx.x;
    const float* xr = x + (size_t)row * Cq;
    float v0 = xr[tid], v1 = xr[tid + 256], v2 = xr[tid + 512];

    __shared__ float red[256];
    red[tid] = v0 + v1 + v2;
    __syncthreads();
    #pragma unroll
    for (int off = 128; off > 0; off >>= 1) {
        if (tid < off) red[tid] += red[tid + off];
        __syncthreads();
    }
    float mu = red[0] * (1.0f / Cq);
    __syncthreads();

    float d0 = v0 - mu, d1 = v1 - mu, d2 = v2 - mu;
    red[tid] = d0*d0 + d1*d1 + d2*d2;
    __syncthreads();
    #pragma unroll
    for (int off = 128; off > 0; off >>= 1) {
        if (tid < off) red[tid] += red[tid + off];
        __syncthreads();
    }
    float rstd = rsqrtf(red[0] * (1.0f / Cq) + 1e-5f);

    float* orow = o + (size_t)row * Cq;
    orow[tid      ] = to_tf32(d0 * rstd * g[tid      ] + b[tid      ]);
    orow[tid + 256] = to_tf32(d1 * rstd * g[tid + 256] + b[tid + 256]);
    orow[tid + 512] = to_tf32(d2 * rstd * g[tid + 512] + b[tid + 512]);
}

// ---------------- tf32 GEMM: 4-stage cp.async pipeline ----------------------
// FUSE: 1 = bias, 2 = bias+gelu (rounded out), 3 = bias+residual, 4 = QKV split
#define GS 4
#define ASTRIDE 20
#define BSTRIDE 136
#define A_TILE_F (128*ASTRIDE)
#define B_TILE_F (16*BSTRIDE)
#define STAGE_F  (A_TILE_F + B_TILE_F)
#define TG_SMEM  (GS*STAGE_F*4)         // 75776 bytes

template<int FUSE>
__global__ __launch_bounds__(256, 2) void tgemm_kernel(const float* __restrict__ A,
                                                       const float* __restrict__ W,
                                                       const float* __restrict__ bias,
                                                       const float* __restrict__ res,
                                                       float* __restrict__ C,
                                                       int M, int N, int K)
{
    extern __shared__ float tsm[];

    const int tid  = threadIdx.x;
    const int lane = tid & 31;
    const int w    = tid >> 5;
    const int g    = lane >> 2;
    const int cc   = lane & 3;
    const int m_warp = (w >> 2) * 64;
    const int n_warp = (w & 3) * 32;

    const int m0 = blockIdx.y * 128;
    const int n0 = blockIdx.x * 128;

    const int aR = tid >> 2;
    const int aK = (tid & 3) << 2;
    const int bR = tid >> 5;
    const int bC = (tid & 31) << 2;

    const int ntiles = K / 16;

    uint32_t a_dst0 = (uint32_t)__cvta_generic_to_shared(&tsm[aR * ASTRIDE + aK]);
    uint32_t a_dst1 = (uint32_t)__cvta_generic_to_shared(&tsm[(aR + 64) * ASTRIDE + aK]);
    uint32_t b_dst0 = (uint32_t)__cvta_generic_to_shared(&tsm[A_TILE_F + bR * BSTRIDE + bC]);
    uint32_t b_dst1 = (uint32_t)__cvta_generic_to_shared(&tsm[A_TILE_F + (bR + 8) * BSTRIDE + bC]);

    const float* a_src0 = &A[(size_t)(m0 + aR) * K + aK];
    const float* a_src1 = &A[(size_t)(m0 + aR + 64) * K + aK];
    const float* b_src0 = &W[(size_t)bR * N + n0 + bC];
    const float* b_src1 = &W[(size_t)(bR + 8) * N + n0 + bC];

    #pragma unroll
    for (int t = 0; t < 3; t++) {
        const uint32_t so = (uint32_t)(t * STAGE_F * 4);
        cpasync16(a_dst0 + so, a_src0 + t * 16);
        cpasync16(a_dst1 + so, a_src1 + t * 16);
        cpasync16(b_dst0 + so, b_src0 + (size_t)t * 16 * N);
        cpasync16(b_dst1 + so, b_src1 + (size_t)t * 16 * N);
        asm volatile("cp.async.commit_group;" ::: "memory");
    }

    float acc[4][4][4] = {};

    for (int t = 0; t < ntiles; t++) {
        asm volatile("cp.async.wait_group 2;" ::: "memory");
        __syncthreads();

        if (t + 3 < ntiles) {
            const int s = (t + 3) & 3;
            const uint32_t so = (uint32_t)(s * STAGE_F * 4);
            const int k0 = (t + 3) * 16;
            cpasync16(a_dst0 + so, a_src0 + k0);
            cpasync16(a_dst1 + so, a_src1 + k0);
            cpasync16(b_dst0 + so, b_src0 + (size_t)k0 * N);
            cpasync16(b_dst1 + so, b_src1 + (size_t)k0 * N);
        }
        asm volatile("cp.async.commit_group;" ::: "memory");

        const float* As = tsm + (t & 3) * STAGE_F;
        const float* Bs = As + A_TILE_F;

        #pragma unroll
        for (int kb = 0; kb < 2; kb++) {
            const int kk = kb * 8;
            uint32_t afr[4][4];
            uint32_t bfr[4][2];
            #pragma unroll
            for (int mf = 0; mf < 4; mf++) {
                const int mb = m_warp + mf * 16;
                afr[mf][0] = __float_as_uint(As[(mb + g    ) * ASTRIDE + kk + cc    ]);
                afr[mf][1] = __float_as_uint(As[(mb + g + 8) * ASTRIDE + kk + cc    ]);
                afr[mf][2] = __float_as_uint(As[(mb + g    ) * ASTRIDE + kk + cc + 4]);
                afr[mf][3] = __float_as_uint(As[(mb + g + 8) * ASTRIDE + kk + cc + 4]);
            }
            #pragma unroll
            for (int nf = 0; nf < 4; nf++) {
                const int nb = n_warp + nf * 8;
                bfr[nf][0] = __float_as_uint(Bs[(kk + cc    ) * BSTRIDE + nb + g]);
                bfr[nf][1] = __float_as_uint(Bs[(kk + cc + 4) * BSTRIDE + nb + g]);
            }
            #pragma unroll
            for (int mf = 0; mf < 4; mf++)
                #pragma unroll
                for (int nf = 0; nf < 4; nf++)
                    mma_tf32(acc[mf][nf], afr[mf], bfr[nf]);
        }
    }

    #pragma unroll
    for (int mf = 0; mf < 4; mf++) {
        #pragma unroll
        for (int nf = 0; nf < 4; nf++) {
            const int n  = n0 + n_warp + nf * 8 + 2 * cc;
            const int r0 = m0 + m_warp + mf * 16 + g;
            const int r1 = r0 + 8;
            float b0 = bias[n], b1 = bias[n + 1];
            float v00 = acc[mf][nf][0] + b0;
            float v01 = acc[mf][nf][1] + b1;
            float v10 = acc[mf][nf][2] + b0;
            float v11 = acc[mf][nf][3] + b1;
            if (FUSE == 2) {
                v00 = to_tf32(gelu_f(v00)); v01 = to_tf32(gelu_f(v01));
                v10 = to_tf32(gelu_f(v10)); v11 = to_tf32(gelu_f(v11));
            }
            if (FUSE == 3) {
                const float2 r0v = *(const float2*)&res[(size_t)r0 * N + n];
                const float2 r1v = *(const float2*)&res[(size_t)r1 * N + n];
                v00 += r0v.x; v01 += r0v.y;
                v10 += r1v.x; v11 += r1v.y;
            }
            if (FUSE == 4) {
                if (n0 < Cq) {                 // Q region: fp32
                    *(float2*)&g_q[(size_t)r0 * Cq + n] = make_float2(v00, v01);
                    *(float2*)&g_q[(size_t)r1 * Cq + n] = make_float2(v10, v11);
                } else if (n0 < 2 * Cq) {      // K region: bf16 [t][col]
                    const int col = n - Cq;
                    *(__nv_bfloat162*)&g_kb[(size_t)r0 * Cq + col] =
                        __floats2bfloat162_rn(v00, v01);
                    *(__nv_bfloat162*)&g_kb[(size_t)r1 * Cq + col] =
                        __floats2bfloat162_rn(v10, v11);
                } else {                       // V region: bf16 transposed [b,h,d][t]
                    const int col = n - 2 * Cq;
                    const int hh = col >> 6, d = col & 63;
                    {
                        const int bb = r0 >> 11, tt = r0 & 2047;
                        const size_t base = (size_t)(bb * Hq + hh) * HDq;
                        g_vT[(base + d    ) * Tq + tt] = __float2bfloat16_rn(v00);
                        g_vT[(base + d + 1) * Tq + tt] = __float2bfloat16_rn(v01);
                    }
                    {
                        const int bb = r1 >> 11, tt = r1 & 2047;
                        const size_t base = (size_t)(bb * Hq + hh) * HDq;
                        g_vT[(base + d    ) * Tq + tt] = __float2bfloat16_rn(v10);
                        g_vT[(base + d + 1) * Tq + tt] = __float2bfloat16_rn(v11);
                    }
                }
            } else {
                *(float2*)&C[(size_t)r0 * N + n] = make_float2(v00, v01);
                *(float2*)&C[(size_t)r1 * N + n] = make_float2(v10, v11);
            }
        }
    }
}

// ---------------- bf16 flash attention (m16n8k16, register-resident P) ------
// 256 threads (8 warps), Q-tile 128, K/V-tile 64, double-buffered cp.async.
#define ATQ 128
#define ATK 64
#define KVB 4096                 // bf16 elements per K or V buffer (64x64)
#define ATT_SMEM (4*KVB*2)       // 32768 bytes

__device__ __forceinline__ void attn_issue_kv(int b, int h, int k0,
                                              __nv_bfloat16* KsBuf,
                                              __nv_bfloat16* VsBuf, int tid)
{
    #pragma unroll
    for (int i = 0; i < 2; i++) {
        const int e  = tid + i * 256;     // 0..511
        const int r  = e >> 3;            // row 0..63
        const int ch = e & 7;             // 16B chunk
        const __nv_bfloat16* ksrc =
            g_kb + (size_t)(b * Tq + k0 + r) * Cq + h * HDq + ch * 8;
        const __nv_bfloat16* vsrc =
            g_vT + ((size_t)(b * Hq + h) * HDq + r) * Tq + k0 + ch * 8;
        const int sw = (ch ^ (r & 7)) << 3;
        cpasync16((uint32_t)__cvta_generic_to_shared(&KsBuf[r * 64 + sw]), ksrc);
        cpasync16((uint32_t)__cvta_generic_to_shared(&VsBuf[r * 64 + sw]), vsrc);
    }
}

__global__ __launch_bounds__(256, 2) void fattn_kernel(float* __restrict__ y)
{
    extern __shared__ __nv_bfloat16 smb[];
    __nv_bfloat16* Ks = smb;              // [2][64][64]
    __nv_bfloat16* Vs = smb + 2 * KVB;    // [2][64][64]

    const int tid  = threadIdx.x;
    const int lane = tid & 31;
    const int w    = tid >> 5;
    const int g    = lane >> 2;
    const int cc   = lane & 3;
    const int b    = blockIdx.z, h = blockIdx.y;
    const int q0   = (int)(gridDim.x - 1 - blockIdx.x) * ATQ;  // long blocks first
    const int mrow = w * 16;

    attn_issue_kv(b, h, 0, Ks, Vs, tid);
    asm volatile("cp.async.commit_group;" ::: "memory");

    // Q fragments from global (scaled by 1/8, bf16)
    uint32_t aq[4][4];
    {
        const float* q0p = g_q + (size_t)(b * Tq + q0 + mrow + g) * Cq + h * HDq;
        const float* q1p = q0p + 8 * Cq;
        #pragma unroll
        for (int ks = 0; ks < 4; ks++) {
            const int d0 = 16 * ks + 2 * cc;
            float2 x00 = *(const float2*)(q0p + d0);
            float2 x10 = *(const float2*)(q1p + d0);
            float2 x01 = *(const float2*)(q0p + d0 + 8);
            float2 x11 = *(const float2*)(q1p + d0 + 8);
            aq[ks][0] = bf2u(__floats2bfloat162_rn(x00.x * 0.125f, x00.y * 0.125f));
            aq[ks][1] = bf2u(__floats2bfloat162_rn(x10.x * 0.125f, x10.y * 0.125f));
            aq[ks][2] = bf2u(__floats2bfloat162_rn(x01.x * 0.125f, x01.y * 0.125f));
            aq[ks][3] = bf2u(__floats2bfloat162_rn(x11.x * 0.125f, x11.y * 0.125f));
        }
    }

    float of[8][4] = {};
    float m_a = -1e30f, m_b = -1e30f, l_a = 0.0f, l_b = 0.0f;

    const int ntiles = (q0 + ATQ) / ATK;
    for (int t = 0; t < ntiles; t++) {
        const int buf = t & 1;
        const int k0  = t * ATK;
        const bool has_next = (t + 1) < ntiles;
        if (has_next) {
            attn_issue_kv(b, h, (t + 1) * ATK,
                          Ks + (buf ^ 1) * KVB, Vs + (buf ^ 1) * KVB, tid);
            asm volatile("cp.async.commit_group;" ::: "memory");
            asm volatile("cp.async.wait_group 1;" ::: "memory");
        } else {
            asm volatile("cp.async.wait_group 0;" ::: "memory");
        }
        __syncthreads();

        if (k0 <= q0 + mrow + 15) {
            const uint32_t* KsW = (const uint32_t*)(Ks + buf * KVB);
            const uint32_t* VsW = (const uint32_t*)(Vs + buf * KVB);

            // ---- S = Q @ K^T
            float sf[8][4] = {};
            #pragma unroll
            for (int ks = 0; ks < 4; ks++) {
                #pragma unroll
                for (int nf = 0; nf < 8; nf++) {
                    const int rk = nf * 8 + g;
                    uint32_t bb[2];
                    bb[0] = KsW[rk * 32 + (((2 * ks    ) ^ g) << 2) + cc];
                    bb[1] = KsW[rk * 32 + (((2 * ks + 1) ^ g) << 2) + cc];
                    mma_bf16(sf[nf], aq[ks], bb);
                }
            }

            if (k0 + ATK - 1 > q0 + mrow) {   // diagonal: mask key k0+col > q0+row
                const int ta = q0 - k0 + mrow + g;
                const int tb = ta + 8;
                #pragma unroll
                for (int nf = 0; nf < 8; nf++) {
                    const int col0 = nf * 8 + 2 * cc;
                    if (col0     > ta) sf[nf][0] = -1e30f;
                    if (col0 + 1 > ta) sf[nf][1] = -1e30f;
                    if (col0     > tb) sf[nf][2] = -1e30f;
                    if (col0 + 1 > tb) sf[nf][3] = -1e30f;
                }
            }

            // ---- tile row max
            float mt_a = -1e30f, mt_b = -1e30f;
            #pragma unroll
            for (int nf = 0; nf < 8; nf++) {
                mt_a = fmaxf(mt_a, fmaxf(sf[nf][0], sf[nf][1]));
                mt_b = fmaxf(mt_b, fmaxf(sf[nf][2], sf[nf][3]));
            }
            mt_a = fmaxf(mt_a, __shfl_xor_sync(0xffffffffu, mt_a, 1));
            mt_a = fmaxf(mt_a, __shfl_xor_sync(0xffffffffu, mt_a, 2));
            mt_b = fmaxf(mt_b, __shfl_xor_sync(0xffffffffu, mt_b, 1));
            mt_b = fmaxf(mt_b, __shfl_xor_sync(0xffffffffu, mt_b, 2));

            // ---- online softmax update
            const float mn_a = fmaxf(m_a, mt_a), mn_b = fmaxf(m_b, mt_b);
            const float ca = __expf(m_a - mn_a), cb = __expf(m_b - mn_b);
            m_a = mn_a; m_b = mn_b;
            l_a *= ca; l_b *= cb;
            #pragma unroll
            for (int nd = 0; nd < 8; nd++) {
                of[nd][0] *= ca; of[nd][1] *= ca;
                of[nd][2] *= cb; of[nd][3] *= cb;
            }

            // ---- P = exp(S - m), bf16-rounded, packed directly into A-frags
            uint32_t pa[4][4];
            float sa = 0.0f, sb = 0.0f;
            #pragma unroll
            for (int nf = 0; nf < 8; nf++) {
                const float p0 = __expf(sf[nf][0] - m_a);
                const float p1 = __expf(sf[nf][1] - m_a);
                const float p2 = __expf(sf[nf][2] - m_b);
                const float p3 = __expf(sf[nf][3] - m_b);
                const __nv_bfloat162 hA = __floats2bfloat162_rn(p0, p1);
                const __nv_bfloat162 hB = __floats2bfloat162_rn(p2, p3);
                const float2 rA = __bfloat1622float2(hA);
                const float2 rB = __bfloat1622float2(hB);
                sa += rA.x + rA.y;
                sb += rB.x + rB.y;
                const int ks = nf >> 1;
                if (nf & 1) { pa[ks][2] = bf2u(hA); pa[ks][3] = bf2u(hB); }
                else        { pa[ks][0] = bf2u(hA); pa[ks][1] = bf2u(hB); }
            }
            sa += __shfl_xor_sync(0xffffffffu, sa, 1);
            sa += __shfl_xor_sync(0xffffffffu, sa, 2);
            sb += __shfl_xor_sync(0xffffffffu, sb, 1);
            sb += __shfl_xor_sync(0xffffffffu, sb, 2);
            l_a += sa; l_b += sb;

            // ---- O += P @ V (V stored [d][key] -> b-frags natural)
            #pragma unroll
            for (int ks = 0; ks < 4; ks++) {
                #pragma unroll
                for (int nd = 0; nd < 8; nd++) {
                    const int rv = nd * 8 + g;
                    uint32_t bb[2];
                    bb[0] = VsW[rv * 32 + (((2 * ks    ) ^ g) << 2) + cc];
                    bb[1] = VsW[rv * 32 + (((2 * ks + 1) ^ g) << 2) + cc];
                    mma_bf16(of[nd], pa[ks], bb);
                }
            }
        }
        __syncthreads();
    }

    const float ia = 1.0f / l_a, ib = 1.0f / l_b;
    const int ra = q0 + mrow + g, rb = ra + 8;
    #pragma unroll
    for (int nd = 0; nd < 8; nd++) {
        const int col = h * HDq + nd * 8 + 2 * cc;
        *(float2*)&y[((size_t)(b * Tq) + ra) * Cq + col] =
            make_float2(to_tf32(of[nd][0] * ia), to_tf32(of[nd][1] * ia));
        *(float2*)&y[((size_t)(b * Tq) + rb) * Cq + col] =
            make_float2(to_tf32(of[nd][2] * ib), to_tf32(of[nd][3] * ib));
    }
}

// ---------------- launch ----------------------------------------------------
extern "C" void kernel_launch(void* const* d_in, const int* in_sizes, int n_in,
                              void* d_out, int out_size)
{
    (void)in_sizes; (void)n_in; (void)out_size;
    const float* x           = (const float*)d_in[0];
    const float* ln1_g       = (const float*)d_in[1];
    const float* ln1_b       = (const float*)d_in[2];
    const float* w_attn      = (const float*)d_in[3];
    const float* b_attn      = (const float*)d_in[4];
    const float* w_attn_proj = (const float*)d_in[5];
    const float* b_attn_proj = (const float*)d_in[6];
    const float* ln2_g       = (const float*)d_in[7];
    const float* ln2_b       = (const float*)d_in[8];
    const float* w_fc        = (const float*)d_in[9];
    const float* b_fc        = (const float*)d_in[10];
    const float* w_mlp_proj  = (const float*)d_in[11];
    const float* b_mlp_proj  = (const float*)d_in[12];
    float* out = (float*)d_out;

    float *ln1, *q, *att, *x1, *ln2, *fc, *w1, *w2, *w3, *w4;
    cudaGetSymbolAddress((void**)&ln1, g_ln1);
    cudaGetSymbolAddress((void**)&q,   g_q);
    cudaGetSymbolAddress((void**)&att, g_att);
    cudaGetSymbolAddress((void**)&x1,  g_x1);
    cudaGetSymbolAddress((void**)&ln2, g_ln2);
    cudaGetSymbolAddress((void**)&fc,  g_fc);
    cudaGetSymbolAddress((void**)&w1,  g_w_attn);
    cudaGetSymbolAddress((void**)&w2,  g_w_ap);
    cudaGetSymbolAddress((void**)&w3,  g_w_fc);
    cudaGetSymbolAddress((void**)&w4,  g_w_mp);

    cudaFuncSetAttribute(fattn_kernel,
                         cudaFuncAttributeMaxDynamicSharedMemorySize, ATT_SMEM);
    cudaFuncSetAttribute(tgemm_kernel<2>,
                         cudaFuncAttributeMaxDynamicSharedMemorySize, TG_SMEM);
    cudaFuncSetAttribute(tgemm_kernel<3>,
                         cudaFuncAttributeMaxDynamicSharedMemorySize, TG_SMEM);
    cudaFuncSetAttribute(tgemm_kernel<4>,
                         cudaFuncAttributeMaxDynamicSharedMemorySize, TG_SMEM);

    // 0. RNA-round weights into scratch
    round_kernel<<<(Cq*C3/4 + 255)/256, 256>>>(w_attn, w1, Cq*C3/4);
    round_kernel<<<(Cq*Cq/4 + 255)/256, 256>>>(w_attn_proj, w2, Cq*Cq/4);
    round_kernel<<<(Cq*C4/4 + 255)/256, 256>>>(w_fc, w3, Cq*C4/4);
    round_kernel<<<(Cq*C4/4 + 255)/256, 256>>>(w_mlp_proj, w4, Cq*C4/4);

    // 1. LN1 (tf32-rounded out)
    ln_kernel<<<Mrows, 256>>>(x, ln1_g, ln1_b, ln1);
    // 2. QKV GEMM, split writer: Q fp32, K bf16, V bf16-transposed
    tgemm_kernel<4><<<dim3(C3 / 128, Mrows / 128), 256, TG_SMEM>>>(ln1, w1, b_attn,
                                                                   nullptr, q, Mrows, C3, Cq);
    // 3. bf16 flash attention -> att (tf32-rounded)
    fattn_kernel<<<dim3(Tq / ATQ, Hq, Bq), 256, ATT_SMEM>>>(att);
    // 4. x1 = x + att @ w_attn_proj + b_attn_proj
    tgemm_kernel<3><<<dim3(Cq / 128, Mrows / 128), 256, TG_SMEM>>>(att, w2, b_attn_proj,
                                                                   x, x1, Mrows, Cq, Cq);
    // 5. LN2 (tf32-rounded out)
    ln_kernel<<<Mrows, 256>>>(x1, ln2_g, ln2_b, ln2);
    // 6. fc = gelu(ln2 @ w_fc + b_fc), tf32-rounded
    tgemm_kernel<2><<<dim3(C4 / 128, Mrows / 128), 256, TG_SMEM>>>(ln2, w3, b_fc,
                                                                   nullptr, fc, Mrows, C4, Cq);
    // 7. out = x1 + fc @ w_mlp_proj + b_mlp_proj
    tgemm_kernel<3><<<dim3(Cq / 128, Mrows / 128), 256, TG_SMEM>>>(fc, w4, b_mlp_proj,
                                                                   x1, out, Mrows, Cq, C4);
}

// round 11
// speedup vs baseline: 1.5218x; 1.5218x over previous
#include <cuda_runtime.h>
#include <cuda_bf16.h>
#include <math.h>
#include <stdint.h>
#include <string.h>

// Problem dims (fixed by reference)
#define Bq 2
#define Tq 2048
#define Cq 768
#define Hq 12
#define HDq 64
#define Mrows (Bq*Tq)          // 4096
#define C3 (3*Cq)              // 2304
#define C4 (4*Cq)              // 3072

// ---------------- scratch (device globals; no allocations allowed) ----------
__device__ float g_ln1[Mrows*Cq];
__device__ float g_qkv[(size_t)Mrows*C3];
__device__ float g_att[Mrows*Cq];
__device__ float g_x1 [Mrows*Cq];
__device__ float g_ln2[Mrows*Cq];
__device__ float g_fc [(size_t)Mrows*C4];
__device__ __nv_bfloat16 g_kb[(size_t)Mrows*Cq];        // K bf16 [t][h*64+d]
__device__ __nv_bfloat16 g_vT[(size_t)Bq*Hq*HDq*Tq];    // V bf16 [b,h,d][t]
// RNA-rounded weights
__device__ float g_w_attn[Cq*C3];
__device__ float g_w_ap  [Cq*Cq];
__device__ float g_w_fc  [Cq*C4];
__device__ float g_w_mp  [(size_t)C4*Cq];

// ---------------- common helpers --------------------------------------------
__device__ __forceinline__ float gelu_f(float x) {
    const float c = 0.7978845608028654f; // sqrt(2/pi)
    float t = tanhf(c * (x + 0.044715f * x * x * x));
    return 0.5f * x * (1.0f + t);
}

__device__ __forceinline__ float to_tf32(float x) {
    uint32_t r;
    asm("cvt.rna.tf32.f32 %0, %1;" : "=r"(r) : "f"(x));
    return __uint_as_float(r);
}

__device__ __forceinline__ void mma_tf32(float* c, const uint32_t* a, const uint32_t* b) {
    asm volatile(
        "mma.sync.aligned.m16n8k8.row.col.f32.tf32.tf32.f32 "
        "{%0,%1,%2,%3}, {%4,%5,%6,%7}, {%8,%9}, {%0,%1,%2,%3};\n"
        : "+f"(c[0]), "+f"(c[1]), "+f"(c[2]), "+f"(c[3])
        : "r"(a[0]), "r"(a[1]), "r"(a[2]), "r"(a[3]), "r"(b[0]), "r"(b[1]));
}

__device__ __forceinline__ void mma_bf16(float* c, const uint32_t* a, const uint32_t* b) {
    asm volatile(
        "mma.sync.aligned.m16n8k16.row.col.f32.bf16.bf16.f32 "
        "{%0,%1,%2,%3}, {%4,%5,%6,%7}, {%8,%9}, {%0,%1,%2,%3};\n"
        : "+f"(c[0]), "+f"(c[1]), "+f"(c[2]), "+f"(c[3])
        : "r"(a[0]), "r"(a[1]), "r"(a[2]), "r"(a[3]), "r"(b[0]), "r"(b[1]));
}

__device__ __forceinline__ void cpasync16(uint32_t dst, const void* src) {
    asm volatile("cp.async.cg.shared.global [%0], [%1], 16;" :: "r"(dst), "l"(src));
}

__device__ __forceinline__ uint32_t bf2u(__nv_bfloat162 h) {
    uint32_t u; memcpy(&u, &h, 4); return u;
}

// ---------------- weight rounding prep --------------------------------------
__global__ __launch_bounds__(256) void round_kernel(const float* __restrict__ in,
                                                    float* __restrict__ out, int n4)
{
    int i = blockIdx.x * 256 + threadIdx.x;
    if (i < n4) {
        float4 v = ((const float4*)in)[i];
        v.x = to_tf32(v.x); v.y = to_tf32(v.y);
        v.z = to_tf32(v.z); v.w = to_tf32(v.w);
        ((float4*)out)[i] = v;
    }
}

// ---------------- K pack: qkv K region -> bf16 [t][c], coalesced ------------
__global__ __launch_bounds__(256) void kpack_kernel()
{
    const int i = (blockIdx.x * 256 + threadIdx.x) * 4;   // elem index in [0, Mrows*Cq)
    const int t = i / Cq, c = i % Cq;
    const float4 v = *(const float4*)&g_qkv[(size_t)t * C3 + Cq + c];
    *(__nv_bfloat162*)&g_kb[(size_t)t * Cq + c    ] = __floats2bfloat162_rn(v.x, v.y);
    *(__nv_bfloat162*)&g_kb[(size_t)t * Cq + c + 2] = __floats2bfloat162_rn(v.z, v.w);
}

// ---------------- V transpose: qkv V region -> bf16 [b,h,d][t] --------------
__global__ __launch_bounds__(256) void vtrans_kernel()
{
    __shared__ float tile[32][33];
    const int tx = threadIdx.x & 31, ty = threadIdx.x >> 5;   // 32x8
    const int t0 = blockIdx.x * 32;
    const int d0 = blockIdx.y * 32;
    const int bh = blockIdx.z;
    const int b = bh / Hq, h = bh % Hq;

    #pragma unroll
    for (int j = 0; j < 32; j += 8)
        tile[ty + j][tx] =
            g_qkv[(size_t)(b * Tq + t0 + ty + j) * C3 + 2 * Cq + h * HDq + d0 + tx];
    __syncthreads();
    #pragma unroll
    for (int j = 0; j < 32; j += 8)
        g_vT[((size_t)(bh) * HDq + d0 + ty + j) * Tq + t0 + tx] =
            __float2bfloat16_rn(tile[tx][ty + j]);
}

// ---------------- LayerNorm: one block per row (tf32-rounded output) --------
__global__ __launch_bounds__(256) void ln_kernel(const float* __restrict__ x,
                                                 const float* __restrict__ g,
                                                 const float* __restrict__ b,
                                                 float* __restrict__ o)
{
    int row = blockIdx.x;
    int tid = threadIdx.x;
    const float* xr = x + (size_t)row * Cq;
    float v0 = xr[tid], v1 = xr[tid + 256], v2 = xr[tid + 512];

    __shared__ float red[256];
    red[tid] = v0 + v1 + v2;
    __syncthreads();
    #pragma unroll
    for (int off = 128; off > 0; off >>= 1) {
        if (tid < off) red[tid] += red[tid + off];
        __syncthreads();
    }
    float mu = red[0] * (1.0f / Cq);
    __syncthreads();

    float d0 = v0 - mu, d1 = v1 - mu, d2 = v2 - mu;
    red[tid] = d0*d0 + d1*d1 + d2*d2;
    __syncthreads();
    #pragma unroll
    for (int off = 128; off > 0; off >>= 1) {
        if (tid < off) red[tid] += red[tid + off];
        __syncthreads();
    }
    float rstd = rsqrtf(red[0] * (1.0f / Cq) + 1e-5f);

    float* orow = o + (size_t)row * Cq;
    orow[tid      ] = to_tf32(d0 * rstd * g[tid      ] + b[tid      ]);
    orow[tid + 256] = to_tf32(d1 * rstd * g[tid + 256] + b[tid + 256]);
    orow[tid + 512] = to_tf32(d2 * rstd * g[tid + 512] + b[tid + 512]);
}

// ---------------- tf32 GEMM: 4-stage cp.async pipeline ----------------------
// FUSE: 1 = bias, 2 = bias+gelu (rounded out), 3 = bias+residual
#define GS 4
#define ASTRIDE 20
#define BSTRIDE 136
#define A_TILE_F (128*ASTRIDE)
#define B_TILE_F (16*BSTRIDE)
#define STAGE_F  (A_TILE_F + B_TILE_F)
#define TG_SMEM  (GS*STAGE_F*4)         // 75776 bytes

template<int FUSE>
__global__ __launch_bounds__(256, 2) void tgemm_kernel(const float* __restrict__ A,
                                                       const float* __restrict__ W,
                                                       const float* __restrict__ bias,
                                                       const float* __restrict__ res,
                                                       float* __restrict__ C,
                                                       int M, int N, int K)
{
    extern __shared__ float tsm[];

    const int tid  = threadIdx.x;
    const int lane = tid & 31;
    const int w    = tid >> 5;
    const int g    = lane >> 2;
    const int cc   = lane & 3;
    const int m_warp = (w >> 2) * 64;
    const int n_warp = (w & 3) * 32;

    const int m0 = blockIdx.y * 128;
    const int n0 = blockIdx.x * 128;

    const int aR = tid >> 2;
    const int aK = (tid & 3) << 2;
    const int bR = tid >> 5;
    const int bC = (tid & 31) << 2;

    const int ntiles = K / 16;

    uint32_t a_dst0 = (uint32_t)__cvta_generic_to_shared(&tsm[aR * ASTRIDE + aK]);
    uint32_t a_dst1 = (uint32_t)__cvta_generic_to_shared(&tsm[(aR + 64) * ASTRIDE + aK]);
    uint32_t b_dst0 = (uint32_t)__cvta_generic_to_shared(&tsm[A_TILE_F + bR * BSTRIDE + bC]);
    uint32_t b_dst1 = (uint32_t)__cvta_generic_to_shared(&tsm[A_TILE_F + (bR + 8) * BSTRIDE + bC]);

    const float* a_src0 = &A[(size_t)(m0 + aR) * K + aK];
    const float* a_src1 = &A[(size_t)(m0 + aR + 64) * K + aK];
    const float* b_src0 = &W[(size_t)bR * N + n0 + bC];
    const float* b_src1 = &W[(size_t)(bR + 8) * N + n0 + bC];

    #pragma unroll
    for (int t = 0; t < 3; t++) {
        const uint32_t so = (uint32_t)(t * STAGE_F * 4);
        cpasync16(a_dst0 + so, a_src0 + t * 16);
        cpasync16(a_dst1 + so, a_src1 + t * 16);
        cpasync16(b_dst0 + so, b_src0 + (size_t)t * 16 * N);
        cpasync16(b_dst1 + so, b_src1 + (size_t)t * 16 * N);
        asm volatile("cp.async.commit_group;" ::: "memory");
    }

    float acc[4][4][4] = {};

    for (int t = 0; t < ntiles; t++) {
        asm volatile("cp.async.wait_group 2;" ::: "memory");
        __syncthreads();

        if (t + 3 < ntiles) {
            const int s = (t + 3) & 3;
            const uint32_t so = (uint32_t)(s * STAGE_F * 4);
            const int k0 = (t + 3) * 16;
            cpasync16(a_dst0 + so, a_src0 + k0);
            cpasync16(a_dst1 + so, a_src1 + k0);
            cpasync16(b_dst0 + so, b_src0 + (size_t)k0 * N);
            cpasync16(b_dst1 + so, b_src1 + (size_t)k0 * N);
        }
        asm volatile("cp.async.commit_group;" ::: "memory");

        const float* As = tsm + (t & 3) * STAGE_F;
        const float* Bs = As + A_TILE_F;

        #pragma unroll
        for (int kb = 0; kb < 2; kb++) {
            const int kk = kb * 8;
            uint32_t afr[4][4];
            uint32_t bfr[4][2];
            #pragma unroll
            for (int mf = 0; mf < 4; mf++) {
                const int mb = m_warp + mf * 16;
                afr[mf][0] = __float_as_uint(As[(mb + g    ) * ASTRIDE + kk + cc    ]);
                afr[mf][1] = __float_as_uint(As[(mb + g + 8) * ASTRIDE + kk + cc    ]);
                afr[mf][2] = __float_as_uint(As[(mb + g    ) * ASTRIDE + kk + cc + 4]);
                afr[mf][3] = __float_as_uint(As[(mb + g + 8) * ASTRIDE + kk + cc + 4]);
            }
            #pragma unroll
            for (int nf = 0; nf < 4; nf++) {
                const int nb = n_warp + nf * 8;
                bfr[nf][0] = __float_as_uint(Bs[(kk + cc    ) * BSTRIDE + nb + g]);
                bfr[nf][1] = __float_as_uint(Bs[(kk + cc + 4) * BSTRIDE + nb + g]);
            }
            #pragma unroll
            for (int mf = 0; mf < 4; mf++)
                #pragma unroll
                for (int nf = 0; nf < 4; nf++)
                    mma_tf32(acc[mf][nf], afr[mf], bfr[nf]);
        }
    }

    #pragma unroll
    for (int mf = 0; mf < 4; mf++) {
        #pragma unroll
        for (int nf = 0; nf < 4; nf++) {
            const int n  = n0 + n_warp + nf * 8 + 2 * cc;
            const int r0 = m0 + m_warp + mf * 16 + g;
            const int r1 = r0 + 8;
            float b0 = bias[n], b1 = bias[n + 1];
            float v00 = acc[mf][nf][0] + b0;
            float v01 = acc[mf][nf][1] + b1;
            float v10 = acc[mf][nf][2] + b0;
            float v11 = acc[mf][nf][3] + b1;
            if (FUSE == 2) {
                v00 = to_tf32(gelu_f(v00)); v01 = to_tf32(gelu_f(v01));
                v10 = to_tf32(gelu_f(v10)); v11 = to_tf32(gelu_f(v11));
            }
            if (FUSE == 3) {
                const float2 r0v = *(const float2*)&res[(size_t)r0 * N + n];
                const float2 r1v = *(const float2*)&res[(size_t)r1 * N + n];
                v00 += r0v.x; v01 += r0v.y;
                v10 += r1v.x; v11 += r1v.y;
            }
            *(float2*)&C[(size_t)r0 * N + n] = make_float2(v00, v01);
            *(float2*)&C[(size_t)r1 * N + n] = make_float2(v10, v11);
        }
    }
}

// ---------------- bf16 flash attention (m16n8k16, register-resident P) ------
// 256 threads (8 warps), Q-tile 128, K/V-tile 64, double-buffered cp.async.
#define ATQ 128
#define ATK 64
#define KVB 4096                 // bf16 elements per K or V buffer (64x64)
#define ATT_SMEM (4*KVB*2)       // 32768 bytes

__device__ __forceinline__ void attn_issue_kv(int b, int h, int k0,
                                              __nv_bfloat16* KsBuf,
                                              __nv_bfloat16* VsBuf, int tid)
{
    #pragma unroll
    for (int i = 0; i < 2; i++) {
        const int e  = tid + i * 256;     // 0..511
        const int r  = e >> 3;            // row 0..63
        const int ch = e & 7;             // 16B chunk
        const __nv_bfloat16* ksrc =
            g_kb + (size_t)(b * Tq + k0 + r) * Cq + h * HDq + ch * 8;
        const __nv_bfloat16* vsrc =
            g_vT + ((size_t)(b * Hq + h) * HDq + r) * Tq + k0 + ch * 8;
        const int sw = (ch ^ (r & 7)) << 3;
        cpasync16((uint32_t)__cvta_generic_to_shared(&KsBuf[r * 64 + sw]), ksrc);
        cpasync16((uint32_t)__cvta_generic_to_shared(&VsBuf[r * 64 + sw]), vsrc);
    }
}

__global__ __launch_bounds__(256, 2) void fattn_kernel(const float* __restrict__ qkv,
                                                       float* __restrict__ y)
{
    extern __shared__ __nv_bfloat16 smb[];
    __nv_bfloat16* Ks = smb;              // [2][64][64]
    __nv_bfloat16* Vs = smb + 2 * KVB;    // [2][64][64]

    const int tid  = threadIdx.x;
    const int lane = tid & 31;
    const int w    = tid >> 5;
    const int g    = lane >> 2;
    const int cc   = lane & 3;
    const int b    = blockIdx.z, h = blockIdx.y;
    const int q0   = (int)(gridDim.x - 1 - blockIdx.x) * ATQ;  // long blocks first
    const int mrow = w * 16;

    attn_issue_kv(b, h, 0, Ks, Vs, tid);
    asm volatile("cp.async.commit_group;" ::: "memory");

    // Q fragments from global (scaled by 1/8, bf16)
    uint32_t aq[4][4];
    {
        const float* q0p = qkv + (size_t)(b * Tq + q0 + mrow + g) * C3 + h * HDq;
        const float* q1p = q0p + 8 * C3;
        #pragma unroll
        for (int ks = 0; ks < 4; ks++) {
            const int d0 = 16 * ks + 2 * cc;
            float2 x00 = *(const float2*)(q0p + d0);
            float2 x10 = *(const float2*)(q1p + d0);
            float2 x01 = *(const float2*)(q0p + d0 + 8);
            float2 x11 = *(const float2*)(q1p + d0 + 8);
            aq[ks][0] = bf2u(__floats2bfloat162_rn(x00.x * 0.125f, x00.y * 0.125f));
            aq[ks][1] = bf2u(__floats2bfloat162_rn(x10.x * 0.125f, x10.y * 0.125f));
            aq[ks][2] = bf2u(__floats2bfloat162_rn(x01.x * 0.125f, x01.y * 0.125f));
            aq[ks][3] = bf2u(__floats2bfloat162_rn(x11.x * 0.125f, x11.y * 0.125f));
        }
    }

    float of[8][4] = {};
    float m_a = -1e30f, m_b = -1e30f, l_a = 0.0f, l_b = 0.0f;

    const int ntiles = (q0 + ATQ) / ATK;
    for (int t = 0; t < ntiles; t++) {
        const int buf = t & 1;
        const int k0  = t * ATK;
        const bool has_next = (t + 1) < ntiles;
        if (has_next) {
            attn_issue_kv(b, h, (t + 1) * ATK,
                          Ks + (buf ^ 1) * KVB, Vs + (buf ^ 1) * KVB, tid);
            asm volatile("cp.async.commit_group;" ::: "memory");
            asm volatile("cp.async.wait_group 1;" ::: "memory");
        } else {
            asm volatile("cp.async.wait_group 0;" ::: "memory");
        }
        __syncthreads();

        if (k0 <= q0 + mrow + 15) {
            const uint32_t* KsW = (const uint32_t*)(Ks + buf * KVB);
            const uint32_t* VsW = (const uint32_t*)(Vs + buf * KVB);

            // ---- S = Q @ K^T
            float sf[8][4] = {};
            #pragma unroll
            for (int ks = 0; ks < 4; ks++) {
                #pragma unroll
                for (int nf = 0; nf < 8; nf++) {
                    const int rk = nf * 8 + g;
                    uint32_t bb[2];
                    bb[0] = KsW[rk * 32 + (((2 * ks    ) ^ g) << 2) + cc];
                    bb[1] = KsW[rk * 32 + (((2 * ks + 1) ^ g) << 2) + cc];
                    mma_bf16(sf[nf], aq[ks], bb);
                }
            }

            if (k0 + ATK - 1 > q0 + mrow) {   // diagonal: mask key k0+col > q0+row
                const int ta = q0 - k0 + mrow + g;
                const int tb = ta + 8;
                #pragma unroll
                for (int nf = 0; nf < 8; nf++) {
                    const int col0 = nf * 8 + 2 * cc;
                    if (col0     > ta) sf[nf][0] = -1e30f;
                    if (col0 + 1 > ta) sf[nf][1] = -1e30f;
                    if (col0     > tb) sf[nf][2] = -1e30f;
                    if (col0 + 1 > tb) sf[nf][3] = -1e30f;
                }
            }

            // ---- tile row max
            float mt_a = -1e30f, mt_b = -1e30f;
            #pragma unroll
            for (int nf = 0; nf < 8; nf++) {
                mt_a = fmaxf(mt_a, fmaxf(sf[nf][0], sf[nf][1]));
                mt_b = fmaxf(mt_b, fmaxf(sf[nf][2], sf[nf][3]));
            }
            mt_a = fmaxf(mt_a, __shfl_xor_sync(0xffffffffu, mt_a, 1));
            mt_a = fmaxf(mt_a, __shfl_xor_sync(0xffffffffu, mt_a, 2));
            mt_b = fmaxf(mt_b, __shfl_xor_sync(0xffffffffu, mt_b, 1));
            mt_b = fmaxf(mt_b, __shfl_xor_sync(0xffffffffu, mt_b, 2));

            // ---- online softmax update
            const float mn_a = fmaxf(m_a, mt_a), mn_b = fmaxf(m_b, mt_b);
            const float ca = __expf(m_a - mn_a), cb = __expf(m_b - mn_b);
            m_a = mn_a; m_b = mn_b;
            l_a *= ca; l_b *= cb;
            #pragma unroll
            for (int nd = 0; nd < 8; nd++) {
                of[nd][0] *= ca; of[nd][1] *= ca;
                of[nd][2] *= cb; of[nd][3] *= cb;
            }

            // ---- P = exp(S - m), bf16, packed directly into A-frags
            uint32_t pa[4][4];
            float sa = 0.0f, sb = 0.0f;
            #pragma unroll
            for (int nf = 0; nf < 8; nf++) {
                const float p0 = __expf(sf[nf][0] - m_a);
                const float p1 = __expf(sf[nf][1] - m_a);
                const float p2 = __expf(sf[nf][2] - m_b);
                const float p3 = __expf(sf[nf][3] - m_b);
                const __nv_bfloat162 hA = __floats2bfloat162_rn(p0, p1);
                const __nv_bfloat162 hB = __floats2bfloat162_rn(p2, p3);
                const float2 rA = __bfloat1622float2(hA);
                const float2 rB = __bfloat1622float2(hB);
                sa += rA.x + rA.y;
                sb += rB.x + rB.y;
                const int ks = nf >> 1;
                if (nf & 1) { pa[ks][2] = bf2u(hA); pa[ks][3] = bf2u(hB); }
                else        { pa[ks][0] = bf2u(hA); pa[ks][1] = bf2u(hB); }
            }
            sa += __shfl_xor_sync(0xffffffffu, sa, 1);
            sa += __shfl_xor_sync(0xffffffffu, sa, 2);
            sb += __shfl_xor_sync(0xffffffffu, sb, 1);
            sb += __shfl_xor_sync(0xffffffffu, sb, 2);
            l_a += sa; l_b += sb;

            // ---- O += P @ V (V stored [d][key] -> b-frags natural)
            #pragma unroll
            for (int ks = 0; ks < 4; ks++) {
                #pragma unroll
                for (int nd = 0; nd < 8; nd++) {
                    const int rv = nd * 8 + g;
                    uint32_t bb[2];
                    bb[0] = VsW[rv * 32 + (((2 * ks    ) ^ g) << 2) + cc];
                    bb[1] = VsW[rv * 32 + (((2 * ks + 1) ^ g) << 2) + cc];
                    mma_bf16(of[nd], pa[ks], bb);
                }
            }
        }
        __syncthreads();
    }

    const float ia = 1.0f / l_a, ib = 1.0f / l_b;
    const int ra = q0 + mrow + g, rb = ra + 8;
    #pragma unroll
    for (int nd = 0; nd < 8; nd++) {
        const int col = h * HDq + nd * 8 + 2 * cc;
        *(float2*)&y[((size_t)(b * Tq) + ra) * Cq + col] =
            make_float2(to_tf32(of[nd][0] * ia), to_tf32(of[nd][1] * ia));
        *(float2*)&y[((size_t)(b * Tq) + rb) * Cq + col] =
            make_float2(to_tf32(of[nd][2] * ib), to_tf32(of[nd][3] * ib));
    }
}

// ---------------- launch ----------------------------------------------------
extern "C" void kernel_launch(void* const* d_in, const int* in_sizes, int n_in,
                              void* d_out, int out_size)
{
    (void)in_sizes; (void)n_in; (void)out_size;
    const float* x           = (const float*)d_in[0];
    const float* ln1_g       = (const float*)d_in[1];
    const float* ln1_b       = (const float*)d_in[2];
    const float* w_attn      = (const float*)d_in[3];
    const float* b_attn      = (const float*)d_in[4];
    const float* w_attn_proj = (const float*)d_in[5];
    const float* b_attn_proj = (const float*)d_in[6];
    const float* ln2_g       = (const float*)d_in[7];
    const float* ln2_b       = (const float*)d_in[8];
    const float* w_fc        = (const float*)d_in[9];
    const float* b_fc        = (const float*)d_in[10];
    const float* w_mlp_proj  = (const float*)d_in[11];
    const float* b_mlp_proj  = (const float*)d_in[12];
    float* out = (float*)d_out;

    float *ln1, *qkv, *att, *x1, *ln2, *fc, *w1, *w2, *w3, *w4;
    cudaGetSymbolAddress((void**)&ln1, g_ln1);
    cudaGetSymbolAddress((void**)&qkv, g_qkv);
    cudaGetSymbolAddress((void**)&att, g_att);
    cudaGetSymbolAddress((void**)&x1,  g_x1);
    cudaGetSymbolAddress((void**)&ln2, g_ln2);
    cudaGetSymbolAddress((void**)&fc,  g_fc);
    cudaGetSymbolAddress((void**)&w1,  g_w_attn);
    cudaGetSymbolAddress((void**)&w2,  g_w_ap);
    cudaGetSymbolAddress((void**)&w3,  g_w_fc);
    cudaGetSymbolAddress((void**)&w4,  g_w_mp);

    cudaFuncSetAttribute(fattn_kernel,
                         cudaFuncAttributeMaxDynamicSharedMemorySize, ATT_SMEM);
    cudaFuncSetAttribute(tgemm_kernel<1>,
                         cudaFuncAttributeMaxDynamicSharedMemorySize, TG_SMEM);
    cudaFuncSetAttribute(tgemm_kernel<2>,
                         cudaFuncAttributeMaxDynamicSharedMemorySize, TG_SMEM);
    cudaFuncSetAttribute(tgemm_kernel<3>,
                         cudaFuncAttributeMaxDynamicSharedMemorySize, TG_SMEM);

    // 0. RNA-round weights into scratch
    round_kernel<<<(Cq*C3/4 + 255)/256, 256>>>(w_attn, w1, Cq*C3/4);
    round_kernel<<<(Cq*Cq/4 + 255)/256, 256>>>(w_attn_proj, w2, Cq*Cq/4);
    round_kernel<<<(Cq*C4/4 + 255)/256, 256>>>(w_fc, w3, Cq*C4/4);
    round_kernel<<<(Cq*C4/4 + 255)/256, 256>>>(w_mlp_proj, w4, Cq*C4/4);

    // 1. LN1 (tf32-rounded out)
    ln_kernel<<<Mrows, 256>>>(x, ln1_g, ln1_b, ln1);
    // 2. QKV = ln1 @ w_attn + b_attn  [4096, 2304], plain fp32 out
    tgemm_kernel<1><<<dim3(C3 / 128, Mrows / 128), 256, TG_SMEM>>>(ln1, w1, b_attn,
                                                                   nullptr, qkv, Mrows, C3, Cq);
    // 2b. pack K -> bf16, transpose V -> bf16 (both coalesced)
    kpack_kernel<<<Mrows * Cq / 4 / 256, 256>>>();
    vtrans_kernel<<<dim3(Tq / 32, HDq / 32, Bq * Hq), 256>>>();
    // 3. bf16 flash attention -> att (tf32-rounded)
    fattn_kernel<<<dim3(Tq / ATQ, Hq, Bq), 256, ATT_SMEM>>>(qkv, att);
    // 4. x1 = x + att @ w_attn_proj + b_attn_proj
    tgemm_kernel<3><<<dim3(Cq / 128, Mrows / 128), 256, TG_SMEM>>>(att, w2, b_attn_proj,
                                                                   x, x1, Mrows, Cq, Cq);
    // 5. LN2 (tf32-rounded out)
    ln_kernel<<<Mrows, 256>>>(x1, ln2_g, ln2_b, ln2);
    // 6. fc = gelu(ln2 @ w_fc + b_fc), tf32-rounded
    tgemm_kernel<2><<<dim3(C4 / 128, Mrows / 128), 256, TG_SMEM>>>(ln2, w3, b_fc,
                                                                   nullptr, fc, Mrows, C4, Cq);
    // 7. out = x1 + fc @ w_mlp_proj + b_mlp_proj
    tgemm_kernel<3><<<dim3(Cq / 128, Mrows / 128), 256, TG_SMEM>>>(fc, w4, b_mlp_proj,
                                                                   x1, out, Mrows, Cq, C4);
}

// round 12
// speedup vs baseline: 1.6607x; 1.0913x over previous
#include <cuda_runtime.h>
#include <cuda_bf16.h>
#include <math.h>
#include <stdint.h>
#include <string.h>

// Problem dims (fixed by reference)
#define Bq 2
#define Tq 2048
#define Cq 768
#define Hq 12
#define HDq 64
#define Mrows (Bq*Tq)          // 4096
#define C3 (3*Cq)              // 2304
#define C4 (4*Cq)              // 3072

// ---------------- scratch (device globals; no allocations allowed) ----------
__device__ float g_ln1[Mrows*Cq];
__device__ float g_qkv[(size_t)Mrows*C3];
__device__ float g_att[Mrows*Cq];
__device__ float g_x1 [Mrows*Cq];
__device__ float g_ln2[Mrows*Cq];
__device__ float g_fc [(size_t)Mrows*C4];
__device__ __nv_bfloat16 g_kb[(size_t)Mrows*Cq];        // K bf16 [t][h*64+d]
__device__ __nv_bfloat16 g_vT[(size_t)Bq*Hq*HDq*Tq];    // V bf16 [b,h,d][t]
// RNA-rounded weights
__device__ float g_w_attn[Cq*C3];
__device__ float g_w_ap  [Cq*Cq];
__device__ float g_w_fc  [Cq*C4];
__device__ float g_w_mp  [(size_t)C4*Cq];

// ---------------- common helpers --------------------------------------------
__device__ __forceinline__ float gelu_f(float x) {
    const float c = 0.7978845608028654f; // sqrt(2/pi)
    float t = tanhf(c * (x + 0.044715f * x * x * x));
    return 0.5f * x * (1.0f + t);
}

__device__ __forceinline__ float to_tf32(float x) {
    uint32_t r;
    asm("cvt.rna.tf32.f32 %0, %1;" : "=r"(r) : "f"(x));
    return __uint_as_float(r);
}

__device__ __forceinline__ void mma_tf32(float* c, const uint32_t* a, const uint32_t* b) {
    asm volatile(
        "mma.sync.aligned.m16n8k8.row.col.f32.tf32.tf32.f32 "
        "{%0,%1,%2,%3}, {%4,%5,%6,%7}, {%8,%9}, {%0,%1,%2,%3};\n"
        : "+f"(c[0]), "+f"(c[1]), "+f"(c[2]), "+f"(c[3])
        : "r"(a[0]), "r"(a[1]), "r"(a[2]), "r"(a[3]), "r"(b[0]), "r"(b[1]));
}

__device__ __forceinline__ void mma_bf16(float* c, const uint32_t* a, const uint32_t* b) {
    asm volatile(
        "mma.sync.aligned.m16n8k16.row.col.f32.bf16.bf16.f32 "
        "{%0,%1,%2,%3}, {%4,%5,%6,%7}, {%8,%9}, {%0,%1,%2,%3};\n"
        : "+f"(c[0]), "+f"(c[1]), "+f"(c[2]), "+f"(c[3])
        : "r"(a[0]), "r"(a[1]), "r"(a[2]), "r"(a[3]), "r"(b[0]), "r"(b[1]));
}

__device__ __forceinline__ void cpasync16(uint32_t dst, const void* src) {
    asm volatile("cp.async.cg.shared.global [%0], [%1], 16;" :: "r"(dst), "l"(src));
}

__device__ __forceinline__ uint32_t bf2u(__nv_bfloat162 h) {
    uint32_t u; memcpy(&u, &h, 4); return u;
}

__device__ __forceinline__ float warp_sum(float v) {
    v += __shfl_xor_sync(0xffffffffu, v, 16);
    v += __shfl_xor_sync(0xffffffffu, v, 8);
    v += __shfl_xor_sync(0xffffffffu, v, 4);
    v += __shfl_xor_sync(0xffffffffu, v, 2);
    v += __shfl_xor_sync(0xffffffffu, v, 1);
    return v;
}

// ---------------- fused weight rounding (all 4 matrices, one launch) --------
#define RN1 (Cq*C3/4)
#define RN2 (Cq*Cq/4)
#define RN3 (Cq*C4/4)
#define RN4 (C4*Cq/4)
#define RTOT (RN1+RN2+RN3+RN4)

__global__ __launch_bounds__(256) void round4_kernel(const float* __restrict__ s1,
                                                     const float* __restrict__ s2,
                                                     const float* __restrict__ s3,
                                                     const float* __restrict__ s4)
{
    int i = blockIdx.x * 256 + threadIdx.x;
    if (i >= RTOT) return;
    const float* src; float* dst; int j = i;
    if (j < RN1)            { src = s1; dst = g_w_attn; }
    else if ((j -= RN1) < RN2) { src = s2; dst = g_w_ap; }
    else if ((j -= RN2) < RN3) { src = s3; dst = g_w_fc; }
    else { j -= RN3;          src = s4; dst = g_w_mp; }
    float4 v = ((const float4*)src)[j];
    v.x = to_tf32(v.x); v.y = to_tf32(v.y);
    v.z = to_tf32(v.z); v.w = to_tf32(v.w);
    ((float4*)dst)[j] = v;
}

// ---------------- K pack: qkv K region -> bf16 [t][c], coalesced ------------
__global__ __launch_bounds__(256) void kpack_kernel()
{
    const int i = (blockIdx.x * 256 + threadIdx.x) * 4;
    const int t = i / Cq, c = i % Cq;
    const float4 v = *(const float4*)&g_qkv[(size_t)t * C3 + Cq + c];
    *(__nv_bfloat162*)&g_kb[(size_t)t * Cq + c    ] = __floats2bfloat162_rn(v.x, v.y);
    *(__nv_bfloat162*)&g_kb[(size_t)t * Cq + c + 2] = __floats2bfloat162_rn(v.z, v.w);
}

// ---------------- V transpose: qkv V region -> bf16 [b,h,d][t] --------------
__global__ __launch_bounds__(256) void vtrans_kernel()
{
    __shared__ float tile[32][33];
    const int tx = threadIdx.x & 31, ty = threadIdx.x >> 5;   // 32x8
    const int t0 = blockIdx.x * 32;
    const int d0 = blockIdx.y * 32;
    const int bh = blockIdx.z;
    const int b = bh / Hq, h = bh % Hq;

    #pragma unroll
    for (int j = 0; j < 32; j += 8)
        tile[ty + j][tx] =
            g_qkv[(size_t)(b * Tq + t0 + ty + j) * C3 + 2 * Cq + h * HDq + d0 + tx];
    __syncthreads();
    #pragma unroll
    for (int j = 0; j < 32; j += 8)
        g_vT[((size_t)(bh) * HDq + d0 + ty + j) * Tq + t0 + tx] =
            __float2bfloat16_rn(tile[tx][ty + j]);
}

// ---------------- LayerNorm: warp per row (tf32-rounded output) -------------
__global__ __launch_bounds__(256) void ln_kernel(const float* __restrict__ x,
                                                 const float* __restrict__ g,
                                                 const float* __restrict__ b,
                                                 float* __restrict__ o)
{
    const int lane = threadIdx.x & 31;
    const int row  = blockIdx.x * 8 + (threadIdx.x >> 5);
    const float4* xr = (const float4*)(x + (size_t)row * Cq);

    float4 v[6];
    float s = 0.0f;
    #pragma unroll
    for (int i = 0; i < 6; i++) {
        v[i] = xr[i * 32 + lane];
        s += v[i].x + v[i].y + v[i].z + v[i].w;
    }
    const float mu = warp_sum(s) * (1.0f / Cq);

    float q = 0.0f;
    #pragma unroll
    for (int i = 0; i < 6; i++) {
        v[i].x -= mu; v[i].y -= mu; v[i].z -= mu; v[i].w -= mu;
        q += v[i].x*v[i].x + v[i].y*v[i].y + v[i].z*v[i].z + v[i].w*v[i].w;
    }
    const float rstd = rsqrtf(warp_sum(q) * (1.0f / Cq) + 1e-5f);

    float4* orow = (float4*)(o + (size_t)row * Cq);
    #pragma unroll
    for (int i = 0; i < 6; i++) {
        const float4 gg = ((const float4*)g)[i * 32 + lane];
        const float4 bb = ((const float4*)b)[i * 32 + lane];
        float4 r;
        r.x = to_tf32(v[i].x * rstd * gg.x + bb.x);
        r.y = to_tf32(v[i].y * rstd * gg.y + bb.y);
        r.z = to_tf32(v[i].z * rstd * gg.z + bb.z);
        r.w = to_tf32(v[i].w * rstd * gg.w + bb.w);
        orow[i * 32 + lane] = r;
    }
}

// ---------------- tf32 GEMM 128x128: 4-stage cp.async pipeline --------------
// FUSE: 1 = bias, 2 = bias+gelu (rounded out), 3 = bias+residual
#define GS 4
#define ASTRIDE 20
#define BSTRIDE 136
#define A_TILE_F (128*ASTRIDE)
#define B_TILE_F (16*BSTRIDE)
#define STAGE_F  (A_TILE_F + B_TILE_F)
#define TG_SMEM  (GS*STAGE_F*4)         // 75776 bytes

template<int FUSE>
__global__ __launch_bounds__(256, 2) void tgemm_kernel(const float* __restrict__ A,
                                                       const float* __restrict__ W,
                                                       const float* __restrict__ bias,
                                                       const float* __restrict__ res,
                                                       float* __restrict__ C,
                                                       int M, int N, int K)
{
    extern __shared__ float tsm[];

    const int tid  = threadIdx.x;
    const int lane = tid & 31;
    const int w    = tid >> 5;
    const int g    = lane >> 2;
    const int cc   = lane & 3;
    const int m_warp = (w >> 2) * 64;
    const int n_warp = (w & 3) * 32;

    const int m0 = blockIdx.y * 128;
    const int n0 = blockIdx.x * 128;

    const int aR = tid >> 2;
    const int aK = (tid & 3) << 2;
    const int bR = tid >> 5;
    const int bC = (tid & 31) << 2;

    const int ntiles = K / 16;

    uint32_t a_dst0 = (uint32_t)__cvta_generic_to_shared(&tsm[aR * ASTRIDE + aK]);
    uint32_t a_dst1 = (uint32_t)__cvta_generic_to_shared(&tsm[(aR + 64) * ASTRIDE + aK]);
    uint32_t b_dst0 = (uint32_t)__cvta_generic_to_shared(&tsm[A_TILE_F + bR * BSTRIDE + bC]);
    uint32_t b_dst1 = (uint32_t)__cvta_generic_to_shared(&tsm[A_TILE_F + (bR + 8) * BSTRIDE + bC]);

    const float* a_src0 = &A[(size_t)(m0 + aR) * K + aK];
    const float* a_src1 = &A[(size_t)(m0 + aR + 64) * K + aK];
    const float* b_src0 = &W[(size_t)bR * N + n0 + bC];
    const float* b_src1 = &W[(size_t)(bR + 8) * N + n0 + bC];

    #pragma unroll
    for (int t = 0; t < 3; t++) {
        const uint32_t so = (uint32_t)(t * STAGE_F * 4);
        cpasync16(a_dst0 + so, a_src0 + t * 16);
        cpasync16(a_dst1 + so, a_src1 + t * 16);
        cpasync16(b_dst0 + so, b_src0 + (size_t)t * 16 * N);
        cpasync16(b_dst1 + so, b_src1 + (size_t)t * 16 * N);
        asm volatile("cp.async.commit_group;" ::: "memory");
    }

    float acc[4][4][4] = {};

    for (int t = 0; t < ntiles; t++) {
        asm volatile("cp.async.wait_group 2;" ::: "memory");
        __syncthreads();

        if (t + 3 < ntiles) {
            const int s = (t + 3) & 3;
            const uint32_t so = (uint32_t)(s * STAGE_F * 4);
            const int k0 = (t + 3) * 16;
            cpasync16(a_dst0 + so, a_src0 + k0);
            cpasync16(a_dst1 + so, a_src1 + k0);
            cpasync16(b_dst0 + so, b_src0 + (size_t)k0 * N);
            cpasync16(b_dst1 + so, b_src1 + (size_t)k0 * N);
        }
        asm volatile("cp.async.commit_group;" ::: "memory");

        const float* As = tsm + (t & 3) * STAGE_F;
        const float* Bs = As + A_TILE_F;

        #pragma unroll
        for (int kb = 0; kb < 2; kb++) {
            const int kk = kb * 8;
            uint32_t afr[4][4];
            uint32_t bfr[4][2];
            #pragma unroll
            for (int mf = 0; mf < 4; mf++) {
                const int mb = m_warp + mf * 16;
                afr[mf][0] = __float_as_uint(As[(mb + g    ) * ASTRIDE + kk + cc    ]);
                afr[mf][1] = __float_as_uint(As[(mb + g + 8) * ASTRIDE + kk + cc    ]);
                afr[mf][2] = __float_as_uint(As[(mb + g    ) * ASTRIDE + kk + cc + 4]);
                afr[mf][3] = __float_as_uint(As[(mb + g + 8) * ASTRIDE + kk + cc + 4]);
            }
            #pragma unroll
            for (int nf = 0; nf < 4; nf++) {
                const int nb = n_warp + nf * 8;
                bfr[nf][0] = __float_as_uint(Bs[(kk + cc    ) * BSTRIDE + nb + g]);
                bfr[nf][1] = __float_as_uint(Bs[(kk + cc + 4) * BSTRIDE + nb + g]);
            }
            #pragma unroll
            for (int mf = 0; mf < 4; mf++)
                #pragma unroll
                for (int nf = 0; nf < 4; nf++)
                    mma_tf32(acc[mf][nf], afr[mf], bfr[nf]);
        }
    }

    #pragma unroll
    for (int mf = 0; mf < 4; mf++) {
        #pragma unroll
        for (int nf = 0; nf < 4; nf++) {
            const int n  = n0 + n_warp + nf * 8 + 2 * cc;
            const int r0 = m0 + m_warp + mf * 16 + g;
            const int r1 = r0 + 8;
            float b0 = bias[n], b1 = bias[n + 1];
            float v00 = acc[mf][nf][0] + b0;
            float v01 = acc[mf][nf][1] + b1;
            float v10 = acc[mf][nf][2] + b0;
            float v11 = acc[mf][nf][3] + b1;
            if (FUSE == 2) {
                v00 = to_tf32(gelu_f(v00)); v01 = to_tf32(gelu_f(v01));
                v10 = to_tf32(gelu_f(v10)); v11 = to_tf32(gelu_f(v11));
            }
            if (FUSE == 3) {
                const float2 r0v = *(const float2*)&res[(size_t)r0 * N + n];
                const float2 r1v = *(const float2*)&res[(size_t)r1 * N + n];
                v00 += r0v.x; v01 += r0v.y;
                v10 += r1v.x; v11 += r1v.y;
            }
            *(float2*)&C[(size_t)r0 * N + n] = make_float2(v00, v01);
            *(float2*)&C[(size_t)r1 * N + n] = make_float2(v10, v11);
        }
    }
}

// ---------------- tf32 GEMM 64x128: for N=768 GEMMs (more CTAs, 3/SM) -------
#define A64_TILE_F (64*ASTRIDE)                 // 1280 floats
#define STAGE64_F  (A64_TILE_F + B_TILE_F)      // 3456 floats
#define TG64_SMEM  (GS*STAGE64_F*4)             // 55296 bytes

// FUSE: 3 = bias+residual (only variant needed)
__global__ __launch_bounds__(256, 3) void tgemm64_kernel(const float* __restrict__ A,
                                                         const float* __restrict__ W,
                                                         const float* __restrict__ bias,
                                                         const float* __restrict__ res,
                                                         float* __restrict__ C,
                                                         int M, int N, int K)
{
    extern __shared__ float tsm[];

    const int tid  = threadIdx.x;
    const int lane = tid & 31;
    const int w    = tid >> 5;
    const int g    = lane >> 2;
    const int cc   = lane & 3;
    const int m_warp = (w >> 2) * 32;   // 2 warp-rows of 32
    const int n_warp = (w & 3) * 32;    // 4 warp-cols of 32

    const int m0 = blockIdx.y * 64;
    const int n0 = blockIdx.x * 128;

    const int aR = tid >> 2;            // 0..63
    const int aK = (tid & 3) << 2;
    const int bR = tid >> 5;
    const int bC = (tid & 31) << 2;

    const int ntiles = K / 16;

    uint32_t a_dst = (uint32_t)__cvta_generic_to_shared(&tsm[aR * ASTRIDE + aK]);
    uint32_t b_dst0 = (uint32_t)__cvta_generic_to_shared(&tsm[A64_TILE_F + bR * BSTRIDE + bC]);
    uint32_t b_dst1 = (uint32_t)__cvta_generic_to_shared(&tsm[A64_TILE_F + (bR + 8) * BSTRIDE + bC]);

    const float* a_src = &A[(size_t)(m0 + aR) * K + aK];
    const float* b_src0 = &W[(size_t)bR * N + n0 + bC];
    const float* b_src1 = &W[(size_t)(bR + 8) * N + n0 + bC];

    #pragma unroll
    for (int t = 0; t < 3; t++) {
        const uint32_t so = (uint32_t)(t * STAGE64_F * 4);
        cpasync16(a_dst + so, a_src + t * 16);
        cpasync16(b_dst0 + so, b_src0 + (size_t)t * 16 * N);
        cpasync16(b_dst1 + so, b_src1 + (size_t)t * 16 * N);
        asm volatile("cp.async.commit_group;" ::: "memory");
    }

    float acc[2][4][4] = {};

    for (int t = 0; t < ntiles; t++) {
        asm volatile("cp.async.wait_group 2;" ::: "memory");
        __syncthreads();

        if (t + 3 < ntiles) {
            const int s = (t + 3) & 3;
            const uint32_t so = (uint32_t)(s * STAGE64_F * 4);
            const int k0 = (t + 3) * 16;
            cpasync16(a_dst + so, a_src + k0);
            cpasync16(b_dst0 + so, b_src0 + (size_t)k0 * N);
            cpasync16(b_dst1 + so, b_src1 + (size_t)k0 * N);
        }
        asm volatile("cp.async.commit_group;" ::: "memory");

        const float* As = tsm + (t & 3) * STAGE64_F;
        const float* Bs = As + A64_TILE_F;

        #pragma unroll
        for (int kb = 0; kb < 2; kb++) {
            const int kk = kb * 8;
            uint32_t afr[2][4];
            uint32_t bfr[4][2];
            #pragma unroll
            for (int mf = 0; mf < 2; mf++) {
                const int mb = m_warp + mf * 16;
                afr[mf][0] = __float_as_uint(As[(mb + g    ) * ASTRIDE + kk + cc    ]);
                afr[mf][1] = __float_as_uint(As[(mb + g + 8) * ASTRIDE + kk + cc    ]);
                afr[mf][2] = __float_as_uint(As[(mb + g    ) * ASTRIDE + kk + cc + 4]);
                afr[mf][3] = __float_as_uint(As[(mb + g + 8) * ASTRIDE + kk + cc + 4]);
            }
            #pragma unroll
            for (int nf = 0; nf < 4; nf++) {
                const int nb = n_warp + nf * 8;
                bfr[nf][0] = __float_as_uint(Bs[(kk + cc    ) * BSTRIDE + nb + g]);
                bfr[nf][1] = __float_as_uint(Bs[(kk + cc + 4) * BSTRIDE + nb + g]);
            }
            #pragma unroll
            for (int mf = 0; mf < 2; mf++)
                #pragma unroll
                for (int nf = 0; nf < 4; nf++)
                    mma_tf32(acc[mf][nf], afr[mf], bfr[nf]);
        }
    }

    #pragma unroll
    for (int mf = 0; mf < 2; mf++) {
        #pragma unroll
        for (int nf = 0; nf < 4; nf++) {
            const int n  = n0 + n_warp + nf * 8 + 2 * cc;
            const int r0 = m0 + m_warp + mf * 16 + g;
            const int r1 = r0 + 8;
            float b0 = bias[n], b1 = bias[n + 1];
            float v00 = acc[mf][nf][0] + b0;
            float v01 = acc[mf][nf][1] + b1;
            float v10 = acc[mf][nf][2] + b0;
            float v11 = acc[mf][nf][3] + b1;
            const float2 r0v = *(const float2*)&res[(size_t)r0 * N + n];
            const float2 r1v = *(const float2*)&res[(size_t)r1 * N + n];
            v00 += r0v.x; v01 += r0v.y;
            v10 += r1v.x; v11 += r1v.y;
            *(float2*)&C[(size_t)r0 * N + n] = make_float2(v00, v01);
            *(float2*)&C[(size_t)r1 * N + n] = make_float2(v10, v11);
        }
    }
}

// ---------------- bf16 flash attention (m16n8k16, register-resident P) ------
#define ATQ 128
#define ATK 64
#define KVB 4096                 // bf16 elements per K or V buffer (64x64)
#define ATT_SMEM (4*KVB*2)       // 32768 bytes

__device__ __forceinline__ void attn_issue_kv(int b, int h, int k0,
                                              __nv_bfloat16* KsBuf,
                                              __nv_bfloat16* VsBuf, int tid)
{
    #pragma unroll
    for (int i = 0; i < 2; i++) {
        const int e  = tid + i * 256;
        const int r  = e >> 3;
        const int ch = e & 7;
        const __nv_bfloat16* ksrc =
            g_kb + (size_t)(b * Tq + k0 + r) * Cq + h * HDq + ch * 8;
        const __nv_bfloat16* vsrc =
            g_vT + ((size_t)(b * Hq + h) * HDq + r) * Tq + k0 + ch * 8;
        const int sw = (ch ^ (r & 7)) << 3;
        cpasync16((uint32_t)__cvta_generic_to_shared(&KsBuf[r * 64 + sw]), ksrc);
        cpasync16((uint32_t)__cvta_generic_to_shared(&VsBuf[r * 64 + sw]), vsrc);
    }
}

__global__ __launch_bounds__(256, 2) void fattn_kernel(const float* __restrict__ qkv,
                                                       float* __restrict__ y)
{
    extern __shared__ __nv_bfloat16 smb[];
    __nv_bfloat16* Ks = smb;
    __nv_bfloat16* Vs = smb + 2 * KVB;

    const int tid  = threadIdx.x;
    const int lane = tid & 31;
    const int w    = tid >> 5;
    const int g    = lane >> 2;
    const int cc   = lane & 3;
    const int b    = blockIdx.z, h = blockIdx.y;
    const int q0   = (int)(gridDim.x - 1 - blockIdx.x) * ATQ;
    const int mrow = w * 16;

    attn_issue_kv(b, h, 0, Ks, Vs, tid);
    asm volatile("cp.async.commit_group;" ::: "memory");

    uint32_t aq[4][4];
    {
        const float* q0p = qkv + (size_t)(b * Tq + q0 + mrow + g) * C3 + h * HDq;
        const float* q1p = q0p + 8 * C3;
        #pragma unroll
        for (int ks = 0; ks < 4; ks++) {
            const int d0 = 16 * ks + 2 * cc;
            float2 x00 = *(const float2*)(q0p + d0);
            float2 x10 = *(const float2*)(q1p + d0);
            float2 x01 = *(const float2*)(q0p + d0 + 8);
            float2 x11 = *(const float2*)(q1p + d0 + 8);
            aq[ks][0] = bf2u(__floats2bfloat162_rn(x00.x * 0.125f, x00.y * 0.125f));
            aq[ks][1] = bf2u(__floats2bfloat162_rn(x10.x * 0.125f, x10.y * 0.125f));
            aq[ks][2] = bf2u(__floats2bfloat162_rn(x01.x * 0.125f, x01.y * 0.125f));
            aq[ks][3] = bf2u(__floats2bfloat162_rn(x11.x * 0.125f, x11.y * 0.125f));
        }
    }

    float of[8][4] = {};
    float m_a = -1e30f, m_b = -1e30f, l_a = 0.0f, l_b = 0.0f;

    const int ntiles = (q0 + ATQ) / ATK;
    for (int t = 0; t < ntiles; t++) {
        const int buf = t & 1;
        const int k0  = t * ATK;
        const bool has_next = (t + 1) < ntiles;
        if (has_next) {
            attn_issue_kv(b, h, (t + 1) * ATK,
                          Ks + (buf ^ 1) * KVB, Vs + (buf ^ 1) * KVB, tid);
            asm volatile("cp.async.commit_group;" ::: "memory");
            asm volatile("cp.async.wait_group 1;" ::: "memory");
        } else {
            asm volatile("cp.async.wait_group 0;" ::: "memory");
        }
        __syncthreads();

        if (k0 <= q0 + mrow + 15) {
            const uint32_t* KsW = (const uint32_t*)(Ks + buf * KVB);
            const uint32_t* VsW = (const uint32_t*)(Vs + buf * KVB);

            float sf[8][4] = {};
            #pragma unroll
            for (int ks = 0; ks < 4; ks++) {
                #pragma unroll
                for (int nf = 0; nf < 8; nf++) {
                    const int rk = nf * 8 + g;
                    uint32_t bb[2];
                    bb[0] = KsW[rk * 32 + (((2 * ks    ) ^ g) << 2) + cc];
                    bb[1] = KsW[rk * 32 + (((2 * ks + 1) ^ g) << 2) + cc];
                    mma_bf16(sf[nf], aq[ks], bb);
                }
            }

            if (k0 + ATK - 1 > q0 + mrow) {
                const int ta = q0 - k0 + mrow + g;
                const int tb = ta + 8;
                #pragma unroll
                for (int nf = 0; nf < 8; nf++) {
                    const int col0 = nf * 8 + 2 * cc;
                    if (col0     > ta) sf[nf][0] = -1e30f;
                    if (col0 + 1 > ta) sf[nf][1] = -1e30f;
                    if (col0     > tb) sf[nf][2] = -1e30f;
                    if (col0 + 1 > tb) sf[nf][3] = -1e30f;
                }
            }

            float mt_a = -1e30f, mt_b = -1e30f;
            #pragma unroll
            for (int nf = 0; nf < 8; nf++) {
                mt_a = fmaxf(mt_a, fmaxf(sf[nf][0], sf[nf][1]));
                mt_b = fmaxf(mt_b, fmaxf(sf[nf][2], sf[nf][3]));
            }
            mt_a = fmaxf(mt_a, __shfl_xor_sync(0xffffffffu, mt_a, 1));
            mt_a = fmaxf(mt_a, __shfl_xor_sync(0xffffffffu, mt_a, 2));
            mt_b = fmaxf(mt_b, __shfl_xor_sync(0xffffffffu, mt_b, 1));
            mt_b = fmaxf(mt_b, __shfl_xor_sync(0xffffffffu, mt_b, 2));

            const float mn_a = fmaxf(m_a, mt_a), mn_b = fmaxf(m_b, mt_b);
            const float ca = __expf(m_a - mn_a), cb = __expf(m_b - mn_b);
            m_a = mn_a; m_b = mn_b;
            l_a *= ca; l_b *= cb;
            #pragma unroll
            for (int nd = 0; nd < 8; nd++) {
                of[nd][0] *= ca; of[nd][1] *= ca;
                of[nd][2] *= cb; of[nd][3] *= cb;
            }

            uint32_t pa[4][4];
            float sa = 0.0f, sb = 0.0f;
            #pragma unroll
            for (int nf = 0; nf < 8; nf++) {
                const float p0 = __expf(sf[nf][0] - m_a);
                const float p1 = __expf(sf[nf][1] - m_a);
                const float p2 = __expf(sf[nf][2] - m_b);
                const float p3 = __expf(sf[nf][3] - m_b);
                const __nv_bfloat162 hA = __floats2bfloat162_rn(p0, p1);
                const __nv_bfloat162 hB = __floats2bfloat162_rn(p2, p3);
                const float2 rA = __bfloat1622float2(hA);
                const float2 rB = __bfloat1622float2(hB);
                sa += rA.x + rA.y;
                sb += rB.x + rB.y;
                const int ks = nf >> 1;
                if (nf & 1) { pa[ks][2] = bf2u(hA); pa[ks][3] = bf2u(hB); }
                else        { pa[ks][0] = bf2u(hA); pa[ks][1] = bf2u(hB); }
            }
            sa += __shfl_xor_sync(0xffffffffu, sa, 1);
            sa += __shfl_xor_sync(0xffffffffu, sa, 2);
            sb += __shfl_xor_sync(0xffffffffu, sb, 1);
            sb += __shfl_xor_sync(0xffffffffu, sb, 2);
            l_a += sa; l_b += sb;

            #pragma unroll
            for (int ks = 0; ks < 4; ks++) {
                #pragma unroll
                for (int nd = 0; nd < 8; nd++) {
                    const int rv = nd * 8 + g;
                    uint32_t bb[2];
                    bb[0] = VsW[rv * 32 + (((2 * ks    ) ^ g) << 2) + cc];
                    bb[1] = VsW[rv * 32 + (((2 * ks + 1) ^ g) << 2) + cc];
                    mma_bf16(of[nd], pa[ks], bb);
                }
            }
        }
        __syncthreads();
    }

    const float ia = 1.0f / l_a, ib = 1.0f / l_b;
    const int ra = q0 + mrow + g, rb = ra + 8;
    #pragma unroll
    for (int nd = 0; nd < 8; nd++) {
        const int col = h * HDq + nd * 8 + 2 * cc;
        *(float2*)&y[((size_t)(b * Tq) + ra) * Cq + col] =
            make_float2(to_tf32(of[nd][0] * ia), to_tf32(of[nd][1] * ia));
        *(float2*)&y[((size_t)(b * Tq) + rb) * Cq + col] =
            make_float2(to_tf32(of[nd][2] * ib), to_tf32(of[nd][3] * ib));
    }
}

// ---------------- launch ----------------------------------------------------
extern "C" void kernel_launch(void* const* d_in, const int* in_sizes, int n_in,
                              void* d_out, int out_size)
{
    (void)in_sizes; (void)n_in; (void)out_size;
    const float* x           = (const float*)d_in[0];
    const float* ln1_g       = (const float*)d_in[1];
    const float* ln1_b       = (const float*)d_in[2];
    const float* w_attn      = (const float*)d_in[3];
    const float* b_attn      = (const float*)d_in[4];
    const float* w_attn_proj = (const float*)d_in[5];
    const float* b_attn_proj = (const float*)d_in[6];
    const float* ln2_g       = (const float*)d_in[7];
    const float* ln2_b       = (const float*)d_in[8];
    const float* w_fc        = (const float*)d_in[9];
    const float* b_fc        = (const float*)d_in[10];
    const float* w_mlp_proj  = (const float*)d_in[11];
    const float* b_mlp_proj  = (const float*)d_in[12];
    float* out = (float*)d_out;

    float *ln1, *qkv, *att, *x1, *ln2, *fc, *w1, *w2, *w3, *w4;
    cudaGetSymbolAddress((void**)&ln1, g_ln1);
    cudaGetSymbolAddress((void**)&qkv, g_qkv);
    cudaGetSymbolAddress((void**)&att, g_att);
    cudaGetSymbolAddress((void**)&x1,  g_x1);
    cudaGetSymbolAddress((void**)&ln2, g_ln2);
    cudaGetSymbolAddress((void**)&fc,  g_fc);
    cudaGetSymbolAddress((void**)&w1,  g_w_attn);
    cudaGetSymbolAddress((void**)&w2,  g_w_ap);
    cudaGetSymbolAddress((void**)&w3,  g_w_fc);
    cudaGetSymbolAddress((void**)&w4,  g_w_mp);

    cudaFuncSetAttribute(fattn_kernel,
                         cudaFuncAttributeMaxDynamicSharedMemorySize, ATT_SMEM);
    cudaFuncSetAttribute(tgemm_kernel<1>,
                         cudaFuncAttributeMaxDynamicSharedMemorySize, TG_SMEM);
    cudaFuncSetAttribute(tgemm_kernel<2>,
                         cudaFuncAttributeMaxDynamicSharedMemorySize, TG_SMEM);
    cudaFuncSetAttribute(tgemm64_kernel,
                         cudaFuncAttributeMaxDynamicSharedMemorySize, TG64_SMEM);

    // 0. RNA-round all weights (one launch)
    round4_kernel<<<(RTOT + 255) / 256, 256>>>(w_attn, w_attn_proj, w_fc, w_mlp_proj);

    // 1. LN1 (warp per row, tf32-rounded out)
    ln_kernel<<<Mrows / 8, 256>>>(x, ln1_g, ln1_b, ln1);
    // 2. QKV = ln1 @ w_attn + b_attn  [4096, 2304]
    tgemm_kernel<1><<<dim3(C3 / 128, Mrows / 128), 256, TG_SMEM>>>(ln1, w1, b_attn,
                                                                   nullptr, qkv, Mrows, C3, Cq);
    // 2b. pack K -> bf16, transpose V -> bf16
    kpack_kernel<<<Mrows * Cq / 4 / 256, 256>>>();
    vtrans_kernel<<<dim3(Tq / 32, HDq / 32, Bq * Hq), 256>>>();
    // 3. bf16 flash attention -> att (tf32-rounded)
    fattn_kernel<<<dim3(Tq / ATQ, Hq, Bq), 256, ATT_SMEM>>>(qkv, att);
    // 4. x1 = x + att @ w_attn_proj + b_attn_proj   (64-row tiles, 384 CTAs)
    tgemm64_kernel<<<dim3(Cq / 128, Mrows / 64), 256, TG64_SMEM>>>(att, w2, b_attn_proj,
                                                                   x, x1, Mrows, Cq, Cq);
    // 5. LN2 (warp per row)
    ln_kernel<<<Mrows / 8, 256>>>(x1, ln2_g, ln2_b, ln2);
    // 6. fc = gelu(ln2 @ w_fc + b_fc), tf32-rounded
    tgemm_kernel<2><<<dim3(C4 / 128, Mrows / 128), 256, TG_SMEM>>>(ln2, w3, b_fc,
                                                                   nullptr, fc, Mrows, C4, Cq);
    // 7. out = x1 + fc @ w_mlp_proj + b_mlp_proj    (64-row tiles, 384 CTAs)
    tgemm64_kernel<<<dim3(Cq / 128, Mrows / 64), 256, TG64_SMEM>>>(fc, w4, b_mlp_proj,
                                                                   x1, out, Mrows, Cq, C4);
}

// round 13
// speedup vs baseline: 1.6618x; 1.0007x over previous
#include <cuda_runtime.h>
#include <cuda_bf16.h>
#include <math.h>
#include <stdint.h>
#include <string.h>

// Problem dims (fixed by reference)
#define Bq 2
#define Tq 2048
#define Cq 768
#define Hq 12
#define HDq 64
#define Mrows (Bq*Tq)          // 4096
#define C3 (3*Cq)              // 2304
#define C4 (4*Cq)              // 3072

// ---------------- scratch (device globals; no allocations allowed) ----------
__device__ float g_ln1[Mrows*Cq];
__device__ float g_qkv[(size_t)Mrows*C3];
__device__ float g_att[Mrows*Cq];
__device__ float g_x1 [Mrows*Cq];
__device__ float g_ln2[Mrows*Cq];
__device__ float g_fc [(size_t)Mrows*C4];
__device__ __nv_bfloat16 g_kb[(size_t)Mrows*Cq];        // K bf16 [t][h*64+d]
__device__ __nv_bfloat16 g_vT[(size_t)Bq*Hq*HDq*Tq];    // V bf16 [b,h,d][t]
// RNA-rounded weights
__device__ float g_w_attn[Cq*C3];
__device__ float g_w_ap  [Cq*Cq];
__device__ float g_w_fc  [Cq*C4];
__device__ float g_w_mp  [(size_t)C4*Cq];

// ---------------- common helpers --------------------------------------------
__device__ __forceinline__ float gelu_f(float x) {
    const float c = 0.7978845608028654f; // sqrt(2/pi)
    float t = tanhf(c * (x + 0.044715f * x * x * x));
    return 0.5f * x * (1.0f + t);
}

__device__ __forceinline__ float to_tf32(float x) {
    uint32_t r;
    asm("cvt.rna.tf32.f32 %0, %1;" : "=r"(r) : "f"(x));
    return __uint_as_float(r);
}

__device__ __forceinline__ void mma_tf32(float* c, const uint32_t* a, const uint32_t* b) {
    asm volatile(
        "mma.sync.aligned.m16n8k8.row.col.f32.tf32.tf32.f32 "
        "{%0,%1,%2,%3}, {%4,%5,%6,%7}, {%8,%9}, {%0,%1,%2,%3};\n"
        : "+f"(c[0]), "+f"(c[1]), "+f"(c[2]), "+f"(c[3])
        : "r"(a[0]), "r"(a[1]), "r"(a[2]), "r"(a[3]), "r"(b[0]), "r"(b[1]));
}

__device__ __forceinline__ void mma_bf16(float* c, const uint32_t* a, const uint32_t* b) {
    asm volatile(
        "mma.sync.aligned.m16n8k16.row.col.f32.bf16.bf16.f32 "
        "{%0,%1,%2,%3}, {%4,%5,%6,%7}, {%8,%9}, {%0,%1,%2,%3};\n"
        : "+f"(c[0]), "+f"(c[1]), "+f"(c[2]), "+f"(c[3])
        : "r"(a[0]), "r"(a[1]), "r"(a[2]), "r"(a[3]), "r"(b[0]), "r"(b[1]));
}

__device__ __forceinline__ void cpasync16(uint32_t dst, const void* src) {
    asm volatile("cp.async.cg.shared.global [%0], [%1], 16;" :: "r"(dst), "l"(src));
}

__device__ __forceinline__ uint32_t bf2u(__nv_bfloat162 h) {
    uint32_t u; memcpy(&u, &h, 4); return u;
}

__device__ __forceinline__ float warp_sum(float v) {
    v += __shfl_xor_sync(0xffffffffu, v, 16);
    v += __shfl_xor_sync(0xffffffffu, v, 8);
    v += __shfl_xor_sync(0xffffffffu, v, 4);
    v += __shfl_xor_sync(0xffffffffu, v, 2);
    v += __shfl_xor_sync(0xffffffffu, v, 1);
    return v;
}

// ---------------- prep: weight rounding + LN1, one launch -------------------
#define RN1 (Cq*C3/4)
#define RN2 (Cq*Cq/4)
#define RN3 (Cq*C4/4)
#define RN4 (C4*Cq/4)
#define RTOT (RN1+RN2+RN3+RN4)
#define RBLK (RTOT/256)          // 6912 (exact)
#define LNBLK (Mrows/8)          // 512

__device__ __forceinline__ void ln_body(const float* __restrict__ x,
                                        const float* __restrict__ g,
                                        const float* __restrict__ b,
                                        float* __restrict__ o, int blk)
{
    const int lane = threadIdx.x & 31;
    const int row  = blk * 8 + (threadIdx.x >> 5);
    const float4* xr = (const float4*)(x + (size_t)row * Cq);

    float4 v[6];
    float s = 0.0f;
    #pragma unroll
    for (int i = 0; i < 6; i++) {
        v[i] = xr[i * 32 + lane];
        s += v[i].x + v[i].y + v[i].z + v[i].w;
    }
    const float mu = warp_sum(s) * (1.0f / Cq);

    float q = 0.0f;
    #pragma unroll
    for (int i = 0; i < 6; i++) {
        v[i].x -= mu; v[i].y -= mu; v[i].z -= mu; v[i].w -= mu;
        q += v[i].x*v[i].x + v[i].y*v[i].y + v[i].z*v[i].z + v[i].w*v[i].w;
    }
    const float rstd = rsqrtf(warp_sum(q) * (1.0f / Cq) + 1e-5f);

    float4* orow = (float4*)(o + (size_t)row * Cq);
    #pragma unroll
    for (int i = 0; i < 6; i++) {
        const float4 gg = ((const float4*)g)[i * 32 + lane];
        const float4 bb = ((const float4*)b)[i * 32 + lane];
        float4 r;
        r.x = to_tf32(v[i].x * rstd * gg.x + bb.x);
        r.y = to_tf32(v[i].y * rstd * gg.y + bb.y);
        r.z = to_tf32(v[i].z * rstd * gg.z + bb.z);
        r.w = to_tf32(v[i].w * rstd * gg.w + bb.w);
        orow[i * 32 + lane] = r;
    }
}

__global__ __launch_bounds__(256) void prep_kernel(const float* __restrict__ s1,
                                                   const float* __restrict__ s2,
                                                   const float* __restrict__ s3,
                                                   const float* __restrict__ s4,
                                                   const float* __restrict__ x,
                                                   const float* __restrict__ ln1_g,
                                                   const float* __restrict__ ln1_b)
{
    if (blockIdx.x >= RBLK) {
        ln_body(x, ln1_g, ln1_b, g_ln1, blockIdx.x - RBLK);
        return;
    }
    int i = blockIdx.x * 256 + threadIdx.x;
    const float* src; float* dst; int j = i;
    if (j < RN1)               { src = s1; dst = g_w_attn; }
    else if ((j -= RN1) < RN2) { src = s2; dst = g_w_ap; }
    else if ((j -= RN2) < RN3) { src = s3; dst = g_w_fc; }
    else { j -= RN3;             src = s4; dst = g_w_mp; }
    float4 v = ((const float4*)src)[j];
    v.x = to_tf32(v.x); v.y = to_tf32(v.y);
    v.z = to_tf32(v.z); v.w = to_tf32(v.w);
    ((float4*)dst)[j] = v;
}

// ---------------- standalone LN (for LN2) -----------------------------------
__global__ __launch_bounds__(256) void ln_kernel(const float* __restrict__ x,
                                                 const float* __restrict__ g,
                                                 const float* __restrict__ b,
                                                 float* __restrict__ o)
{
    ln_body(x, g, b, o, blockIdx.x);
}

// ---------------- pack: K bf16 copy + V bf16 transpose, one launch ----------
#define KPBLK (Mrows*Cq/4/256)   // 3072
#define VTBLK (((Tq/32)*(HDq/32))*(Bq*Hq))  // 64*2*24 = 3072

__global__ __launch_bounds__(256) void pack_kernel()
{
    if (blockIdx.x < KPBLK) {
        const int i = (blockIdx.x * 256 + threadIdx.x) * 4;
        const int t = i / Cq, c = i % Cq;
        const float4 v = *(const float4*)&g_qkv[(size_t)t * C3 + Cq + c];
        *(__nv_bfloat162*)&g_kb[(size_t)t * Cq + c    ] = __floats2bfloat162_rn(v.x, v.y);
        *(__nv_bfloat162*)&g_kb[(size_t)t * Cq + c + 2] = __floats2bfloat162_rn(v.z, v.w);
        return;
    }
    __shared__ float tile[32][33];
    const int bx = blockIdx.x - KPBLK;
    const int tx = threadIdx.x & 31, ty = threadIdx.x >> 5;   // 32x8
    const int t0 = (bx & 63) * 32;          // 64 t-tiles
    const int d0 = ((bx >> 6) & 1) * 32;    // 2 d-tiles
    const int bh = bx >> 7;                 // 24
    const int b = bh / Hq, h = bh % Hq;

    #pragma unroll
    for (int j = 0; j < 32; j += 8)
        tile[ty + j][tx] =
            g_qkv[(size_t)(b * Tq + t0 + ty + j) * C3 + 2 * Cq + h * HDq + d0 + tx];
    __syncthreads();
    #pragma unroll
    for (int j = 0; j < 32; j += 8)
        g_vT[((size_t)(bh) * HDq + d0 + ty + j) * Tq + t0 + tx] =
            __float2bfloat16_rn(tile[tx][ty + j]);
}

// ---------------- tf32 GEMM 128x128: 4-stage cp.async pipeline --------------
// FUSE: 1 = bias, 2 = bias+gelu (rounded out), 3 = bias+residual
#define GS 4
#define ASTRIDE 20
#define BSTRIDE 136
#define A_TILE_F (128*ASTRIDE)
#define B_TILE_F (16*BSTRIDE)
#define STAGE_F  (A_TILE_F + B_TILE_F)
#define TG_SMEM  (GS*STAGE_F*4)         // 75776 bytes

template<int FUSE>
__global__ __launch_bounds__(256, 2) void tgemm_kernel(const float* __restrict__ A,
                                                       const float* __restrict__ W,
                                                       const float* __restrict__ bias,
                                                       const float* __restrict__ res,
                                                       float* __restrict__ C,
                                                       int M, int N, int K)
{
    extern __shared__ float tsm[];

    const int tid  = threadIdx.x;
    const int lane = tid & 31;
    const int w    = tid >> 5;
    const int g    = lane >> 2;
    const int cc   = lane & 3;
    const int m_warp = (w >> 2) * 64;
    const int n_warp = (w & 3) * 32;

    const int m0 = blockIdx.y * 128;
    const int n0 = blockIdx.x * 128;

    const int aR = tid >> 2;
    const int aK = (tid & 3) << 2;
    const int bR = tid >> 5;
    const int bC = (tid & 31) << 2;

    const int ntiles = K / 16;

    uint32_t a_dst0 = (uint32_t)__cvta_generic_to_shared(&tsm[aR * ASTRIDE + aK]);
    uint32_t a_dst1 = (uint32_t)__cvta_generic_to_shared(&tsm[(aR + 64) * ASTRIDE + aK]);
    uint32_t b_dst0 = (uint32_t)__cvta_generic_to_shared(&tsm[A_TILE_F + bR * BSTRIDE + bC]);
    uint32_t b_dst1 = (uint32_t)__cvta_generic_to_shared(&tsm[A_TILE_F + (bR + 8) * BSTRIDE + bC]);

    const float* a_src0 = &A[(size_t)(m0 + aR) * K + aK];
    const float* a_src1 = &A[(size_t)(m0 + aR + 64) * K + aK];
    const float* b_src0 = &W[(size_t)bR * N + n0 + bC];
    const float* b_src1 = &W[(size_t)(bR + 8) * N + n0 + bC];

    #pragma unroll
    for (int t = 0; t < 3; t++) {
        const uint32_t so = (uint32_t)(t * STAGE_F * 4);
        cpasync16(a_dst0 + so, a_src0 + t * 16);
        cpasync16(a_dst1 + so, a_src1 + t * 16);
        cpasync16(b_dst0 + so, b_src0 + (size_t)t * 16 * N);
        cpasync16(b_dst1 + so, b_src1 + (size_t)t * 16 * N);
        asm volatile("cp.async.commit_group;" ::: "memory");
    }

    float acc[4][4][4] = {};

    for (int t = 0; t < ntiles; t++) {
        asm volatile("cp.async.wait_group 2;" ::: "memory");
        __syncthreads();

        if (t + 3 < ntiles) {
            const int s = (t + 3) & 3;
            const uint32_t so = (uint32_t)(s * STAGE_F * 4);
            const int k0 = (t + 3) * 16;
            cpasync16(a_dst0 + so, a_src0 + k0);
            cpasync16(a_dst1 + so, a_src1 + k0);
            cpasync16(b_dst0 + so, b_src0 + (size_t)k0 * N);
            cpasync16(b_dst1 + so, b_src1 + (size_t)k0 * N);
        }
        asm volatile("cp.async.commit_group;" ::: "memory");

        const float* As = tsm + (t & 3) * STAGE_F;
        const float* Bs = As + A_TILE_F;

        #pragma unroll
        for (int kb = 0; kb < 2; kb++) {
            const int kk = kb * 8;
            uint32_t afr[4][4];
            uint32_t bfr[4][2];
            #pragma unroll
            for (int mf = 0; mf < 4; mf++) {
                const int mb = m_warp + mf * 16;
                afr[mf][0] = __float_as_uint(As[(mb + g    ) * ASTRIDE + kk + cc    ]);
                afr[mf][1] = __float_as_uint(As[(mb + g + 8) * ASTRIDE + kk + cc    ]);
                afr[mf][2] = __float_as_uint(As[(mb + g    ) * ASTRIDE + kk + cc + 4]);
                afr[mf][3] = __float_as_uint(As[(mb + g + 8) * ASTRIDE + kk + cc + 4]);
            }
            #pragma unroll
            for (int nf = 0; nf < 4; nf++) {
                const int nb = n_warp + nf * 8;
                bfr[nf][0] = __float_as_uint(Bs[(kk + cc    ) * BSTRIDE + nb + g]);
                bfr[nf][1] = __float_as_uint(Bs[(kk + cc + 4) * BSTRIDE + nb + g]);
            }
            #pragma unroll
            for (int mf = 0; mf < 4; mf++)
                #pragma unroll
                for (int nf = 0; nf < 4; nf++)
                    mma_tf32(acc[mf][nf], afr[mf], bfr[nf]);
        }
    }

    #pragma unroll
    for (int mf = 0; mf < 4; mf++) {
        #pragma unroll
        for (int nf = 0; nf < 4; nf++) {
            const int n  = n0 + n_warp + nf * 8 + 2 * cc;
            const int r0 = m0 + m_warp + mf * 16 + g;
            const int r1 = r0 + 8;
            float b0 = bias[n], b1 = bias[n + 1];
            float v00 = acc[mf][nf][0] + b0;
            float v01 = acc[mf][nf][1] + b1;
            float v10 = acc[mf][nf][2] + b0;
            float v11 = acc[mf][nf][3] + b1;
            if (FUSE == 2) {
                v00 = to_tf32(gelu_f(v00)); v01 = to_tf32(gelu_f(v01));
                v10 = to_tf32(gelu_f(v10)); v11 = to_tf32(gelu_f(v11));
            }
            if (FUSE == 3) {
                const float2 r0v = *(const float2*)&res[(size_t)r0 * N + n];
                const float2 r1v = *(const float2*)&res[(size_t)r1 * N + n];
                v00 += r0v.x; v01 += r0v.y;
                v10 += r1v.x; v11 += r1v.y;
            }
            *(float2*)&C[(size_t)r0 * N + n] = make_float2(v00, v01);
            *(float2*)&C[(size_t)r1 * N + n] = make_float2(v10, v11);
        }
    }
}

// ---------------- tf32 GEMM 64x128 (N=768 GEMMs, 3 CTAs/SM) -----------------
#define A64_TILE_F (64*ASTRIDE)
#define STAGE64_F  (A64_TILE_F + B_TILE_F)
#define TG64_SMEM  (GS*STAGE64_F*4)             // 55296 bytes

__global__ __launch_bounds__(256, 3) void tgemm64_kernel(const float* __restrict__ A,
                                                         const float* __restrict__ W,
                                                         const float* __restrict__ bias,
                                                         const float* __restrict__ res,
                                                         float* __restrict__ C,
                                                         int M, int N, int K)
{
    extern __shared__ float tsm[];

    const int tid  = threadIdx.x;
    const int lane = tid & 31;
    const int w    = tid >> 5;
    const int g    = lane >> 2;
    const int cc   = lane & 3;
    const int m_warp = (w >> 2) * 32;
    const int n_warp = (w & 3) * 32;

    const int m0 = blockIdx.y * 64;
    const int n0 = blockIdx.x * 128;

    const int aR = tid >> 2;
    const int aK = (tid & 3) << 2;
    const int bR = tid >> 5;
    const int bC = (tid & 31) << 2;

    const int ntiles = K / 16;

    uint32_t a_dst = (uint32_t)__cvta_generic_to_shared(&tsm[aR * ASTRIDE + aK]);
    uint32_t b_dst0 = (uint32_t)__cvta_generic_to_shared(&tsm[A64_TILE_F + bR * BSTRIDE + bC]);
    uint32_t b_dst1 = (uint32_t)__cvta_generic_to_shared(&tsm[A64_TILE_F + (bR + 8) * BSTRIDE + bC]);

    const float* a_src = &A[(size_t)(m0 + aR) * K + aK];
    const float* b_src0 = &W[(size_t)bR * N + n0 + bC];
    const float* b_src1 = &W[(size_t)(bR + 8) * N + n0 + bC];

    #pragma unroll
    for (int t = 0; t < 3; t++) {
        const uint32_t so = (uint32_t)(t * STAGE64_F * 4);
        cpasync16(a_dst + so, a_src + t * 16);
        cpasync16(b_dst0 + so, b_src0 + (size_t)t * 16 * N);
        cpasync16(b_dst1 + so, b_src1 + (size_t)t * 16 * N);
        asm volatile("cp.async.commit_group;" ::: "memory");
    }

    float acc[2][4][4] = {};

    for (int t = 0; t < ntiles; t++) {
        asm volatile("cp.async.wait_group 2;" ::: "memory");
        __syncthreads();

        if (t + 3 < ntiles) {
            const int s = (t + 3) & 3;
            const uint32_t so = (uint32_t)(s * STAGE64_F * 4);
            const int k0 = (t + 3) * 16;
            cpasync16(a_dst + so, a_src + k0);
            cpasync16(b_dst0 + so, b_src0 + (size_t)k0 * N);
            cpasync16(b_dst1 + so, b_src1 + (size_t)k0 * N);
        }
        asm volatile("cp.async.commit_group;" ::: "memory");

        const float* As = tsm + (t & 3) * STAGE64_F;
        const float* Bs = As + A64_TILE_F;

        #pragma unroll
        for (int kb = 0; kb < 2; kb++) {
            const int kk = kb * 8;
            uint32_t afr[2][4];
            uint32_t bfr[4][2];
            #pragma unroll
            for (int mf = 0; mf < 2; mf++) {
                const int mb = m_warp + mf * 16;
                afr[mf][0] = __float_as_uint(As[(mb + g    ) * ASTRIDE + kk + cc    ]);
                afr[mf][1] = __float_as_uint(As[(mb + g + 8) * ASTRIDE + kk + cc    ]);
                afr[mf][2] = __float_as_uint(As[(mb + g    ) * ASTRIDE + kk + cc + 4]);
                afr[mf][3] = __float_as_uint(As[(mb + g + 8) * ASTRIDE + kk + cc + 4]);
            }
            #pragma unroll
            for (int nf = 0; nf < 4; nf++) {
                const int nb = n_warp + nf * 8;
                bfr[nf][0] = __float_as_uint(Bs[(kk + cc    ) * BSTRIDE + nb + g]);
                bfr[nf][1] = __float_as_uint(Bs[(kk + cc + 4) * BSTRIDE + nb + g]);
            }
            #pragma unroll
            for (int mf = 0; mf < 2; mf++)
                #pragma unroll
                for (int nf = 0; nf < 4; nf++)
                    mma_tf32(acc[mf][nf], afr[mf], bfr[nf]);
        }
    }

    #pragma unroll
    for (int mf = 0; mf < 2; mf++) {
        #pragma unroll
        for (int nf = 0; nf < 4; nf++) {
            const int n  = n0 + n_warp + nf * 8 + 2 * cc;
            const int r0 = m0 + m_warp + mf * 16 + g;
            const int r1 = r0 + 8;
            float b0 = bias[n], b1 = bias[n + 1];
            float v00 = acc[mf][nf][0] + b0;
            float v01 = acc[mf][nf][1] + b1;
            float v10 = acc[mf][nf][2] + b0;
            float v11 = acc[mf][nf][3] + b1;
            const float2 r0v = *(const float2*)&res[(size_t)r0 * N + n];
            const float2 r1v = *(const float2*)&res[(size_t)r1 * N + n];
            v00 += r0v.x; v01 += r0v.y;
            v10 += r1v.x; v11 += r1v.y;
            *(float2*)&C[(size_t)r0 * N + n] = make_float2(v00, v01);
            *(float2*)&C[(size_t)r1 * N + n] = make_float2(v10, v11);
        }
    }
}

// ---------------- bf16 flash attention: ATK=128 (2 sub-tiles / barrier) -----
#define ATQ 128
#define ATK 128
#define KVT 8192                 // bf16 elems per K (or V) 128-key tile
#define ATT_SMEM (4*KVT*2)       // 65536 bytes

__device__ __forceinline__ void attn_issue_kv(int b, int h, int k0,
                                              __nv_bfloat16* KsBuf,
                                              __nv_bfloat16* VsBuf, int tid)
{
    #pragma unroll
    for (int i = 0; i < 4; i++) {
        const int e  = tid + i * 256;     // 0..1023
        const int r  = e >> 3;            // 0..127
        const int ch = e & 7;
        // K: sub-tile s = r>>6, row rr = r&63 (key k0 + r)
        {
            const int s = r >> 6, rr = r & 63;
            const __nv_bfloat16* ksrc =
                g_kb + (size_t)(b * Tq + k0 + r) * Cq + h * HDq + ch * 8;
            const int sw = (ch ^ (rr & 7)) << 3;
            cpasync16((uint32_t)__cvta_generic_to_shared(&KsBuf[s * 4096 + rr * 64 + sw]), ksrc);
        }
        // V: d = r&63, sub-tile s = r>>6 (keys k0+s*64 .. +63)
        {
            const int s = r >> 6, d = r & 63;
            const __nv_bfloat16* vsrc =
                g_vT + ((size_t)(b * Hq + h) * HDq + d) * Tq + k0 + s * 64 + ch * 8;
            const int sw = (ch ^ (d & 7)) << 3;
            cpasync16((uint32_t)__cvta_generic_to_shared(&VsBuf[s * 4096 + d * 64 + sw]), vsrc);
        }
    }
}

__global__ __launch_bounds__(256, 2) void fattn_kernel(const float* __restrict__ qkv,
                                                       float* __restrict__ y)
{
    extern __shared__ __nv_bfloat16 smb[];
    __nv_bfloat16* Ks = smb;              // [2][2][64][64]
    __nv_bfloat16* Vs = smb + 2 * KVT;    // [2][2][64][64]

    const int tid  = threadIdx.x;
    const int lane = tid & 31;
    const int w    = tid >> 5;
    const int g    = lane >> 2;
    const int cc   = lane & 3;
    const int b    = blockIdx.z, h = blockIdx.y;
    const int q0   = (int)(gridDim.x - 1 - blockIdx.x) * ATQ;  // long blocks first
    const int mrow = w * 16;

    attn_issue_kv(b, h, 0, Ks, Vs, tid);
    asm volatile("cp.async.commit_group;" ::: "memory");

    // Q fragments from global (scaled by 1/8, bf16)
    uint32_t aq[4][4];
    {
        const float* q0p = qkv + (size_t)(b * Tq + q0 + mrow + g) * C3 + h * HDq;
        const float* q1p = q0p + 8 * C3;
        #pragma unroll
        for (int ks = 0; ks < 4; ks++) {
            const int d0 = 16 * ks + 2 * cc;
            float2 x00 = *(const float2*)(q0p + d0);
            float2 x10 = *(const float2*)(q1p + d0);
            float2 x01 = *(const float2*)(q0p + d0 + 8);
            float2 x11 = *(const float2*)(q1p + d0 + 8);
            aq[ks][0] = bf2u(__floats2bfloat162_rn(x00.x * 0.125f, x00.y * 0.125f));
            aq[ks][1] = bf2u(__floats2bfloat162_rn(x10.x * 0.125f, x10.y * 0.125f));
            aq[ks][2] = bf2u(__floats2bfloat162_rn(x01.x * 0.125f, x01.y * 0.125f));
            aq[ks][3] = bf2u(__floats2bfloat162_rn(x11.x * 0.125f, x11.y * 0.125f));
        }
    }

    float of[8][4] = {};
    float m_a = -1e30f, m_b = -1e30f, l_a = 0.0f, l_b = 0.0f;

    const int ntiles = q0 / ATK + 1;      // 128-key tiles covering 0..q0+127
    for (int t = 0; t < ntiles; t++) {
        const int buf = t & 1;
        const bool has_next = (t + 1) < ntiles;
        if (has_next) {
            attn_issue_kv(b, h, (t + 1) * ATK,
                          Ks + (buf ^ 1) * KVT, Vs + (buf ^ 1) * KVT, tid);
            asm volatile("cp.async.commit_group;" ::: "memory");
            asm volatile("cp.async.wait_group 1;" ::: "memory");
        } else {
            asm volatile("cp.async.wait_group 0;" ::: "memory");
        }
        __syncthreads();

        #pragma unroll
        for (int s = 0; s < 2; s++) {
            const int k0s = t * ATK + s * 64;
            if (k0s > q0 + mrow + 15) break;

            const uint32_t* KsW = (const uint32_t*)(Ks + buf * KVT + s * 4096);
            const uint32_t* VsW = (const uint32_t*)(Vs + buf * KVT + s * 4096);

            // ---- S = Q @ K^T
            float sf[8][4] = {};
            #pragma unroll
            for (int ks = 0; ks < 4; ks++) {
                #pragma unroll
                for (int nf = 0; nf < 8; nf++) {
                    const int rk = nf * 8 + g;
                    uint32_t bb[2];
                    bb[0] = KsW[rk * 32 + (((2 * ks    ) ^ g) << 2) + cc];
                    bb[1] = KsW[rk * 32 + (((2 * ks + 1) ^ g) << 2) + cc];
                    mma_bf16(sf[nf], aq[ks], bb);
                }
            }

            if (k0s + 63 > q0 + mrow) {   // diagonal: mask key k0s+col > q0+row
                const int ta = q0 - k0s + mrow + g;
                const int tb = ta + 8;
                #pragma unroll
                for (int nf = 0; nf < 8; nf++) {
                    const int col0 = nf * 8 + 2 * cc;
                    if (col0     > ta) sf[nf][0] = -1e30f;
                    if (col0 + 1 > ta) sf[nf][1] = -1e30f;
                    if (col0     > tb) sf[nf][2] = -1e30f;
                    if (col0 + 1 > tb) sf[nf][3] = -1e30f;
                }
            }

            // ---- tile row max
            float mt_a = -1e30f, mt_b = -1e30f;
            #pragma unroll
            for (int nf = 0; nf < 8; nf++) {
                mt_a = fmaxf(mt_a, fmaxf(sf[nf][0], sf[nf][1]));
                mt_b = fmaxf(mt_b, fmaxf(sf[nf][2], sf[nf][3]));
            }
            mt_a = fmaxf(mt_a, __shfl_xor_sync(0xffffffffu, mt_a, 1));
            mt_a = fmaxf(mt_a, __shfl_xor_sync(0xffffffffu, mt_a, 2));
            mt_b = fmaxf(mt_b, __shfl_xor_sync(0xffffffffu, mt_b, 1));
            mt_b = fmaxf(mt_b, __shfl_xor_sync(0xffffffffu, mt_b, 2));

            // ---- online softmax update
            const float mn_a = fmaxf(m_a, mt_a), mn_b = fmaxf(m_b, mt_b);
            const float ca = __expf(m_a - mn_a), cb = __expf(m_b - mn_b);
            m_a = mn_a; m_b = mn_b;
            l_a *= ca; l_b *= cb;
            #pragma unroll
            for (int nd = 0; nd < 8; nd++) {
                of[nd][0] *= ca; of[nd][1] *= ca;
                of[nd][2] *= cb; of[nd][3] *= cb;
            }

            // ---- P = exp(S - m), bf16, packed directly into A-frags
            uint32_t pa[4][4];
            float sa = 0.0f, sb = 0.0f;
            #pragma unroll
            for (int nf = 0; nf < 8; nf++) {
                const float p0 = __expf(sf[nf][0] - m_a);
                const float p1 = __expf(sf[nf][1] - m_a);
                const float p2 = __expf(sf[nf][2] - m_b);
                const float p3 = __expf(sf[nf][3] - m_b);
                const __nv_bfloat162 hA = __floats2bfloat162_rn(p0, p1);
                const __nv_bfloat162 hB = __floats2bfloat162_rn(p2, p3);
                const float2 rA = __bfloat1622float2(hA);
                const float2 rB = __bfloat1622float2(hB);
                sa += rA.x + rA.y;
                sb += rB.x + rB.y;
                const int ks = nf >> 1;
                if (nf & 1) { pa[ks][2] = bf2u(hA); pa[ks][3] = bf2u(hB); }
                else        { pa[ks][0] = bf2u(hA); pa[ks][1] = bf2u(hB); }
            }
            sa += __shfl_xor_sync(0xffffffffu, sa, 1);
            sa += __shfl_xor_sync(0xffffffffu, sa, 2);
            sb += __shfl_xor_sync(0xffffffffu, sb, 1);
            sb += __shfl_xor_sync(0xffffffffu, sb, 2);
            l_a += sa; l_b += sb;

            // ---- O += P @ V (V stored [d][key] -> b-frags natural)
            #pragma unroll
            for (int ks = 0; ks < 4; ks++) {
                #pragma unroll
                for (int nd = 0; nd < 8; nd++) {
                    const int rv = nd * 8 + g;
                    uint32_t bb[2];
                    bb[0] = VsW[rv * 32 + (((2 * ks    ) ^ g) << 2) + cc];
                    bb[1] = VsW[rv * 32 + (((2 * ks + 1) ^ g) << 2) + cc];
                    mma_bf16(of[nd], pa[ks], bb);
                }
            }
        }
        __syncthreads();
    }

    const float ia = 1.0f / l_a, ib = 1.0f / l_b;
    const int ra = q0 + mrow + g, rb = ra + 8;
    #pragma unroll
    for (int nd = 0; nd < 8; nd++) {
        const int col = h * HDq + nd * 8 + 2 * cc;
        *(float2*)&y[((size_t)(b * Tq) + ra) * Cq + col] =
            make_float2(to_tf32(of[nd][0] * ia), to_tf32(of[nd][1] * ia));
        *(float2*)&y[((size_t)(b * Tq) + rb) * Cq + col] =
            make_float2(to_tf32(of[nd][2] * ib), to_tf32(of[nd][3] * ib));
    }
}

// ---------------- launch ----------------------------------------------------
extern "C" void kernel_launch(void* const* d_in, const int* in_sizes, int n_in,
                              void* d_out, int out_size)
{
    (void)in_sizes; (void)n_in; (void)out_size;
    const float* x           = (const float*)d_in[0];
    const float* ln1_g       = (const float*)d_in[1];
    const float* ln1_b       = (const float*)d_in[2];
    const float* w_attn      = (const float*)d_in[3];
    const float* b_attn      = (const float*)d_in[4];
    const float* w_attn_proj = (const float*)d_in[5];
    const float* b_attn_proj = (const float*)d_in[6];
    const float* ln2_g       = (const float*)d_in[7];
    const float* ln2_b       = (const float*)d_in[8];
    const float* w_fc        = (const float*)d_in[9];
    const float* b_fc        = (const float*)d_in[10];
    const float* w_mlp_proj  = (const float*)d_in[11];
    const float* b_mlp_proj  = (const float*)d_in[12];
    float* out = (float*)d_out;

    float *ln1, *qkv, *att, *x1, *ln2, *fc, *w1, *w2, *w3, *w4;
    cudaGetSymbolAddress((void**)&ln1, g_ln1);
    cudaGetSymbolAddress((void**)&qkv, g_qkv);
    cudaGetSymbolAddress((void**)&att, g_att);
    cudaGetSymbolAddress((void**)&x1,  g_x1);
    cudaGetSymbolAddress((void**)&ln2, g_ln2);
    cudaGetSymbolAddress((void**)&fc,  g_fc);
    cudaGetSymbolAddress((void**)&w1,  g_w_attn);
    cudaGetSymbolAddress((void**)&w2,  g_w_ap);
    cudaGetSymbolAddress((void**)&w3,  g_w_fc);
    cudaGetSymbolAddress((void**)&w4,  g_w_mp);

    cudaFuncSetAttribute(fattn_kernel,
                         cudaFuncAttributeMaxDynamicSharedMemorySize, ATT_SMEM);
    cudaFuncSetAttribute(tgemm_kernel<1>,
                         cudaFuncAttributeMaxDynamicSharedMemorySize, TG_SMEM);
    cudaFuncSetAttribute(tgemm_kernel<2>,
                         cudaFuncAttributeMaxDynamicSharedMemorySize, TG_SMEM);
    cudaFuncSetAttribute(tgemm64_kernel,
                         cudaFuncAttributeMaxDynamicSharedMemorySize, TG64_SMEM);

    // 1. prep: weight RNA-round + LN1 in one launch
    prep_kernel<<<RBLK + LNBLK, 256>>>(w_attn, w_attn_proj, w_fc, w_mlp_proj,
                                       x, ln1_g, ln1_b);
    // 2. QKV = ln1 @ w_attn + b_attn  [4096, 2304]
    tgemm_kernel<1><<<dim3(C3 / 128, Mrows / 128), 256, TG_SMEM>>>(ln1, w1, b_attn,
                                                                   nullptr, qkv, Mrows, C3, Cq);
    // 3. pack: K->bf16 + V->bf16 transposed, one launch
    pack_kernel<<<KPBLK + VTBLK, 256>>>();
    // 4. bf16 flash attention (4th launch -> ncu capture window)
    fattn_kernel<<<dim3(Tq / ATQ, Hq, Bq), 256, ATT_SMEM>>>(qkv, att);
    // 5. x1 = x + att @ w_attn_proj + b_attn_proj
    tgemm64_kernel<<<dim3(Cq / 128, Mrows / 64), 256, TG64_SMEM>>>(att, w2, b_attn_proj,
                                                                   x, x1, Mrows, Cq, Cq);
    // 6. LN2
    ln_kernel<<<Mrows / 8, 256>>>(x1, ln2_g, ln2_b, ln2);
    // 7. fc = gelu(ln2 @ w_fc + b_fc)
    tgemm_kernel<2><<<dim3(C4 / 128, Mrows / 128), 256, TG_SMEM>>>(ln2, w3, b_fc,
                                                                   nullptr, fc, Mrows, C4, Cq);
    // 8. out = x1 + fc @ w_mlp_proj + b_mlp_proj
    tgemm64_kernel<<<dim3(Cq / 128, Mrows / 64), 256, TG64_SMEM>>>(fc, w4, b_mlp_proj,
                                                                   x1, out, Mrows, Cq, C4);
}

// round 14
// speedup vs baseline: 1.7491x; 1.0526x over previous
#include <cuda_runtime.h>
#include <cuda_bf16.h>
#include <math.h>
#include <stdint.h>
#include <string.h>

// Problem dims (fixed by reference)
#define Bq 2
#define Tq 2048
#define Cq 768
#define Hq 12
#define HDq 64
#define Mrows (Bq*Tq)          // 4096
#define C3 (3*Cq)              // 2304
#define C4 (4*Cq)              // 3072

// ---------------- scratch (device globals; no allocations allowed) ----------
__device__ float g_ln1[Mrows*Cq];
__device__ float g_qkv[(size_t)Mrows*C3];
__device__ float g_att[Mrows*Cq];
__device__ float g_x1 [Mrows*Cq];
__device__ float g_ln2[Mrows*Cq];
__device__ float g_fc [(size_t)Mrows*C4];
__device__ __nv_bfloat16 g_kb[(size_t)Mrows*Cq];        // K bf16 [t][h*64+d]
__device__ __nv_bfloat16 g_vT[(size_t)Bq*Hq*HDq*Tq];    // V bf16 [b,h,d][t]
// RNA-rounded weights
__device__ float g_w_attn[Cq*C3];
__device__ float g_w_ap  [Cq*Cq];
__device__ float g_w_fc  [Cq*C4];
__device__ float g_w_mp  [(size_t)C4*Cq];

// ---------------- common helpers --------------------------------------------
__device__ __forceinline__ float gelu_f(float x) {
    const float c = 0.7978845608028654f; // sqrt(2/pi)
    float t = tanhf(c * (x + 0.044715f * x * x * x));
    return 0.5f * x * (1.0f + t);
}

__device__ __forceinline__ float to_tf32(float x) {
    uint32_t r;
    asm("cvt.rna.tf32.f32 %0, %1;" : "=r"(r) : "f"(x));
    return __uint_as_float(r);
}

__device__ __forceinline__ void mma_tf32(float* c, const uint32_t* a, const uint32_t* b) {
    asm volatile(
        "mma.sync.aligned.m16n8k8.row.col.f32.tf32.tf32.f32 "
        "{%0,%1,%2,%3}, {%4,%5,%6,%7}, {%8,%9}, {%0,%1,%2,%3};\n"
        : "+f"(c[0]), "+f"(c[1]), "+f"(c[2]), "+f"(c[3])
        : "r"(a[0]), "r"(a[1]), "r"(a[2]), "r"(a[3]), "r"(b[0]), "r"(b[1]));
}

__device__ __forceinline__ void mma_bf16(float* c, const uint32_t* a, const uint32_t* b) {
    asm volatile(
        "mma.sync.aligned.m16n8k16.row.col.f32.bf16.bf16.f32 "
        "{%0,%1,%2,%3}, {%4,%5,%6,%7}, {%8,%9}, {%0,%1,%2,%3};\n"
        : "+f"(c[0]), "+f"(c[1]), "+f"(c[2]), "+f"(c[3])
        : "r"(a[0]), "r"(a[1]), "r"(a[2]), "r"(a[3]), "r"(b[0]), "r"(b[1]));
}

__device__ __forceinline__ void cpasync16(uint32_t dst, const void* src) {
    asm volatile("cp.async.cg.shared.global [%0], [%1], 16;" :: "r"(dst), "l"(src));
}

__device__ __forceinline__ uint32_t bf2u(__nv_bfloat162 h) {
    uint32_t u; memcpy(&u, &h, 4); return u;
}

__device__ __forceinline__ float warp_sum(float v) {
    v += __shfl_xor_sync(0xffffffffu, v, 16);
    v += __shfl_xor_sync(0xffffffffu, v, 8);
    v += __shfl_xor_sync(0xffffffffu, v, 4);
    v += __shfl_xor_sync(0xffffffffu, v, 2);
    v += __shfl_xor_sync(0xffffffffu, v, 1);
    return v;
}

// ---------------- weight rounding: two halves, two launches ------------------
__global__ __launch_bounds__(256) void round2_kernel(const float* __restrict__ s1,
                                                     float* __restrict__ d1, int n1,
                                                     const float* __restrict__ s2,
                                                     float* __restrict__ d2, int n2)
{
    int i = blockIdx.x * 256 + threadIdx.x;
    const float* src; float* dst;
    if (i < n1) { src = s1; dst = d1; }
    else { i -= n1; if (i >= n2) return; src = s2; dst = d2; }
    float4 v = ((const float4*)src)[i];
    v.x = to_tf32(v.x); v.y = to_tf32(v.y);
    v.z = to_tf32(v.z); v.w = to_tf32(v.w);
    ((float4*)dst)[i] = v;
}

// ---------------- LayerNorm: warp per row (tf32-rounded output) -------------
__global__ __launch_bounds__(256) void ln_kernel(const float* __restrict__ x,
                                                 const float* __restrict__ g,
                                                 const float* __restrict__ b,
                                                 float* __restrict__ o)
{
    const int lane = threadIdx.x & 31;
    const int row  = blockIdx.x * 8 + (threadIdx.x >> 5);
    const float4* xr = (const float4*)(x + (size_t)row * Cq);

    float4 v[6];
    float s = 0.0f;
    #pragma unroll
    for (int i = 0; i < 6; i++) {
        v[i] = xr[i * 32 + lane];
        s += v[i].x + v[i].y + v[i].z + v[i].w;
    }
    const float mu = warp_sum(s) * (1.0f / Cq);

    float q = 0.0f;
    #pragma unroll
    for (int i = 0; i < 6; i++) {
        v[i].x -= mu; v[i].y -= mu; v[i].z -= mu; v[i].w -= mu;
        q += v[i].x*v[i].x + v[i].y*v[i].y + v[i].z*v[i].z + v[i].w*v[i].w;
    }
    const float rstd = rsqrtf(warp_sum(q) * (1.0f / Cq) + 1e-5f);

    float4* orow = (float4*)(o + (size_t)row * Cq);
    #pragma unroll
    for (int i = 0; i < 6; i++) {
        const float4 gg = ((const float4*)g)[i * 32 + lane];
        const float4 bb = ((const float4*)b)[i * 32 + lane];
        float4 r;
        r.x = to_tf32(v[i].x * rstd * gg.x + bb.x);
        r.y = to_tf32(v[i].y * rstd * gg.y + bb.y);
        r.z = to_tf32(v[i].z * rstd * gg.z + bb.z);
        r.w = to_tf32(v[i].w * rstd * gg.w + bb.w);
        orow[i * 32 + lane] = r;
    }
}

// ---------------- pack: K bf16 copy + V bf16 transpose, one launch ----------
#define KPBLK (Mrows*Cq/4/256)   // 3072
#define VTBLK (((Tq/32)*(HDq/32))*(Bq*Hq))  // 3072

__global__ __launch_bounds__(256) void pack_kernel()
{
    if (blockIdx.x < KPBLK) {
        const int i = (blockIdx.x * 256 + threadIdx.x) * 4;
        const int t = i / Cq, c = i % Cq;
        const float4 v = *(const float4*)&g_qkv[(size_t)t * C3 + Cq + c];
        *(__nv_bfloat162*)&g_kb[(size_t)t * Cq + c    ] = __floats2bfloat162_rn(v.x, v.y);
        *(__nv_bfloat162*)&g_kb[(size_t)t * Cq + c + 2] = __floats2bfloat162_rn(v.z, v.w);
        return;
    }
    __shared__ float tile[32][33];
    const int bx = blockIdx.x - KPBLK;
    const int tx = threadIdx.x & 31, ty = threadIdx.x >> 5;   // 32x8
    const int t0 = (bx & 63) * 32;
    const int d0 = ((bx >> 6) & 1) * 32;
    const int bh = bx >> 7;
    const int b = bh / Hq, h = bh % Hq;

    #pragma unroll
    for (int j = 0; j < 32; j += 8)
        tile[ty + j][tx] =
            g_qkv[(size_t)(b * Tq + t0 + ty + j) * C3 + 2 * Cq + h * HDq + d0 + tx];
    __syncthreads();
    #pragma unroll
    for (int j = 0; j < 32; j += 8)
        g_vT[((size_t)(bh) * HDq + d0 + ty + j) * Tq + t0 + tx] =
            __float2bfloat16_rn(tile[tx][ty + j]);
}

// ---------------- tf32 GEMM 128x128: BK=32, 3-stage cp.async ----------------
// FUSE: 1 = bias, 2 = bias+gelu (rounded out)
#define AS32 36
#define BS32 136
#define A32_TILE (128*AS32)            // 4608 floats
#define B32_TILE (32*BS32)             // 4352 floats
#define ST32 (A32_TILE + B32_TILE)     // 8960 floats
#define TG_SMEM (3*ST32*4)             // 107520 bytes

template<int FUSE>
__global__ __launch_bounds__(256, 2) void tgemm_kernel(const float* __restrict__ A,
                                                       const float* __restrict__ W,
                                                       const float* __restrict__ bias,
                                                       const float* __restrict__ res,
                                                       float* __restrict__ C,
                                                       int M, int N, int K)
{
    extern __shared__ float tsm[];

    const int tid  = threadIdx.x;
    const int lane = tid & 31;
    const int w    = tid >> 5;
    const int g    = lane >> 2;
    const int cc   = lane & 3;
    const int m_warp = (w >> 2) * 64;
    const int n_warp = (w & 3) * 32;

    const int m0 = blockIdx.y * 128;
    const int n0 = blockIdx.x * 128;

    const int ntiles = K / 32;

    // per-thread 4 A chunks + 4 B chunks
    uint32_t a_dst[4], b_dst[4];
    const float* a_srcb[4];
    const float* b_srcb[4];
    #pragma unroll
    for (int i = 0; i < 4; i++) {
        const int e  = tid + i * 256;       // 0..1023
        const int ar = e >> 3;              // 0..127
        const int ac = (e & 7) << 2;        // 0..28
        a_dst[i]  = (uint32_t)__cvta_generic_to_shared(&tsm[ar * AS32 + ac]);
        a_srcb[i] = &A[(size_t)(m0 + ar) * K + ac];
        const int br = e >> 5;              // 0..31
        const int bc = (e & 31) << 2;       // 0..124
        b_dst[i]  = (uint32_t)__cvta_generic_to_shared(&tsm[A32_TILE + br * BS32 + bc]);
        b_srcb[i] = &W[(size_t)br * N + n0 + bc];
    }

    // prologue: 2 stages
    #pragma unroll
    for (int t = 0; t < 2; t++) {
        const uint32_t so = (uint32_t)(t * ST32 * 4);
        const int k0 = t * 32;
        #pragma unroll
        for (int i = 0; i < 4; i++) {
            cpasync16(a_dst[i] + so, a_srcb[i] + k0);
            cpasync16(b_dst[i] + so, b_srcb[i] + (size_t)k0 * N);
        }
        asm volatile("cp.async.commit_group;" ::: "memory");
    }

    float acc[4][4][4] = {};

    for (int t = 0; t < ntiles; t++) {
        if (t + 1 < ntiles) {
            asm volatile("cp.async.wait_group 1;" ::: "memory");
        } else {
            asm volatile("cp.async.wait_group 0;" ::: "memory");
        }
        __syncthreads();

        if (t + 2 < ntiles) {
            const int s = (t + 2) % 3;
            const uint32_t so = (uint32_t)(s * ST32 * 4);
            const int k0 = (t + 2) * 32;
            #pragma unroll
            for (int i = 0; i < 4; i++) {
                cpasync16(a_dst[i] + so, a_srcb[i] + k0);
                cpasync16(b_dst[i] + so, b_srcb[i] + (size_t)k0 * N);
            }
        }
        asm volatile("cp.async.commit_group;" ::: "memory");

        const float* As = tsm + (t % 3) * ST32;
        const float* Bs = As + A32_TILE;

        #pragma unroll
        for (int kb = 0; kb < 4; kb++) {
            const int kk = kb * 8;
            uint32_t afr[4][4];
            uint32_t bfr[4][2];
            #pragma unroll
            for (int mf = 0; mf < 4; mf++) {
                const int mb = m_warp + mf * 16;
                afr[mf][0] = __float_as_uint(As[(mb + g    ) * AS32 + kk + cc    ]);
                afr[mf][1] = __float_as_uint(As[(mb + g + 8) * AS32 + kk + cc    ]);
                afr[mf][2] = __float_as_uint(As[(mb + g    ) * AS32 + kk + cc + 4]);
                afr[mf][3] = __float_as_uint(As[(mb + g + 8) * AS32 + kk + cc + 4]);
            }
            #pragma unroll
            for (int nf = 0; nf < 4; nf++) {
                const int nb = n_warp + nf * 8;
                bfr[nf][0] = __float_as_uint(Bs[(kk + cc    ) * BS32 + nb + g]);
                bfr[nf][1] = __float_as_uint(Bs[(kk + cc + 4) * BS32 + nb + g]);
            }
            #pragma unroll
            for (int mf = 0; mf < 4; mf++)
                #pragma unroll
                for (int nf = 0; nf < 4; nf++)
                    mma_tf32(acc[mf][nf], afr[mf], bfr[nf]);
        }
    }

    #pragma unroll
    for (int mf = 0; mf < 4; mf++) {
        #pragma unroll
        for (int nf = 0; nf < 4; nf++) {
            const int n  = n0 + n_warp + nf * 8 + 2 * cc;
            const int r0 = m0 + m_warp + mf * 16 + g;
            const int r1 = r0 + 8;
            float b0 = bias[n], b1 = bias[n + 1];
            float v00 = acc[mf][nf][0] + b0;
            float v01 = acc[mf][nf][1] + b1;
            float v10 = acc[mf][nf][2] + b0;
            float v11 = acc[mf][nf][3] + b1;
            if (FUSE == 2) {
                v00 = to_tf32(gelu_f(v00)); v01 = to_tf32(gelu_f(v01));
                v10 = to_tf32(gelu_f(v10)); v11 = to_tf32(gelu_f(v11));
            }
            if (FUSE == 3) {
                const float2 r0v = *(const float2*)&res[(size_t)r0 * N + n];
                const float2 r1v = *(const float2*)&res[(size_t)r1 * N + n];
                v00 += r0v.x; v01 += r0v.y;
                v10 += r1v.x; v11 += r1v.y;
            }
            *(float2*)&C[(size_t)r0 * N + n] = make_float2(v00, v01);
            *(float2*)&C[(size_t)r1 * N + n] = make_float2(v10, v11);
        }
    }
}

// ---------------- tf32 GEMM 64x128 (N=768 GEMMs, 3 CTAs/SM, BK=16) ----------
#define GS 4
#define ASTRIDE 20
#define BSTRIDE 136
#define B_TILE_F (16*BSTRIDE)
#define A64_TILE_F (64*ASTRIDE)
#define STAGE64_F  (A64_TILE_F + B_TILE_F)
#define TG64_SMEM  (GS*STAGE64_F*4)             // 55296 bytes

__global__ __launch_bounds__(256, 3) void tgemm64_kernel(const float* __restrict__ A,
                                                         const float* __restrict__ W,
                                                         const float* __restrict__ bias,
                                                         const float* __restrict__ res,
                                                         float* __restrict__ C,
                                                         int M, int N, int K)
{
    extern __shared__ float tsm[];

    const int tid  = threadIdx.x;
    const int lane = tid & 31;
    const int w    = tid >> 5;
    const int g    = lane >> 2;
    const int cc   = lane & 3;
    const int m_warp = (w >> 2) * 32;
    const int n_warp = (w & 3) * 32;

    const int m0 = blockIdx.y * 64;
    const int n0 = blockIdx.x * 128;

    const int aR = tid >> 2;
    const int aK = (tid & 3) << 2;
    const int bR = tid >> 5;
    const int bC = (tid & 31) << 2;

    const int ntiles = K / 16;

    uint32_t a_dst = (uint32_t)__cvta_generic_to_shared(&tsm[aR * ASTRIDE + aK]);
    uint32_t b_dst0 = (uint32_t)__cvta_generic_to_shared(&tsm[A64_TILE_F + bR * BSTRIDE + bC]);
    uint32_t b_dst1 = (uint32_t)__cvta_generic_to_shared(&tsm[A64_TILE_F + (bR + 8) * BSTRIDE + bC]);

    const float* a_src = &A[(size_t)(m0 + aR) * K + aK];
    const float* b_src0 = &W[(size_t)bR * N + n0 + bC];
    const float* b_src1 = &W[(size_t)(bR + 8) * N + n0 + bC];

    #pragma unroll
    for (int t = 0; t < 3; t++) {
        const uint32_t so = (uint32_t)(t * STAGE64_F * 4);
        cpasync16(a_dst + so, a_src + t * 16);
        cpasync16(b_dst0 + so, b_src0 + (size_t)t * 16 * N);
        cpasync16(b_dst1 + so, b_src1 + (size_t)t * 16 * N);
        asm volatile("cp.async.commit_group;" ::: "memory");
    }

    float acc[2][4][4] = {};

    for (int t = 0; t < ntiles; t++) {
        asm volatile("cp.async.wait_group 2;" ::: "memory");
        __syncthreads();

        if (t + 3 < ntiles) {
            const int s = (t + 3) & 3;
            const uint32_t so = (uint32_t)(s * STAGE64_F * 4);
            const int k0 = (t + 3) * 16;
            cpasync16(a_dst + so, a_src + k0);
            cpasync16(b_dst0 + so, b_src0 + (size_t)k0 * N);
            cpasync16(b_dst1 + so, b_src1 + (size_t)k0 * N);
        }
        asm volatile("cp.async.commit_group;" ::: "memory");

        const float* As = tsm + (t & 3) * STAGE64_F;
        const float* Bs = As + A64_TILE_F;

        #pragma unroll
        for (int kb = 0; kb < 2; kb++) {
            const int kk = kb * 8;
            uint32_t afr[2][4];
            uint32_t bfr[4][2];
            #pragma unroll
            for (int mf = 0; mf < 2; mf++) {
                const int mb = m_warp + mf * 16;
                afr[mf][0] = __float_as_uint(As[(mb + g    ) * ASTRIDE + kk + cc    ]);
                afr[mf][1] = __float_as_uint(As[(mb + g + 8) * ASTRIDE + kk + cc    ]);
                afr[mf][2] = __float_as_uint(As[(mb + g    ) * ASTRIDE + kk + cc + 4]);
                afr[mf][3] = __float_as_uint(As[(mb + g + 8) * ASTRIDE + kk + cc + 4]);
            }
            #pragma unroll
            for (int nf = 0; nf < 4; nf++) {
                const int nb = n_warp + nf * 8;
                bfr[nf][0] = __float_as_uint(Bs[(kk + cc    ) * BSTRIDE + nb + g]);
                bfr[nf][1] = __float_as_uint(Bs[(kk + cc + 4) * BSTRIDE + nb + g]);
            }
            #pragma unroll
            for (int mf = 0; mf < 2; mf++)
                #pragma unroll
                for (int nf = 0; nf < 4; nf++)
                    mma_tf32(acc[mf][nf], afr[mf], bfr[nf]);
        }
    }

    #pragma unroll
    for (int mf = 0; mf < 2; mf++) {
        #pragma unroll
        for (int nf = 0; nf < 4; nf++) {
            const int n  = n0 + n_warp + nf * 8 + 2 * cc;
            const int r0 = m0 + m_warp + mf * 16 + g;
            const int r1 = r0 + 8;
            float b0 = bias[n], b1 = bias[n + 1];
            float v00 = acc[mf][nf][0] + b0;
            float v01 = acc[mf][nf][1] + b1;
            float v10 = acc[mf][nf][2] + b0;
            float v11 = acc[mf][nf][3] + b1;
            const float2 r0v = *(const float2*)&res[(size_t)r0 * N + n];
            const float2 r1v = *(const float2*)&res[(size_t)r1 * N + n];
            v00 += r0v.x; v01 += r0v.y;
            v10 += r1v.x; v11 += r1v.y;
            *(float2*)&C[(size_t)r0 * N + n] = make_float2(v00, v01);
            *(float2*)&C[(size_t)r1 * N + n] = make_float2(v10, v11);
        }
    }
}

// ---------------- bf16 flash attention: ATK=128 (2 sub-tiles / barrier) -----
#define ATQ 128
#define ATK 128
#define KVT 8192                 // bf16 elems per K (or V) 128-key tile
#define ATT_SMEM (4*KVT*2)       // 65536 bytes

__device__ __forceinline__ void attn_issue_kv(int b, int h, int k0,
                                              __nv_bfloat16* KsBuf,
                                              __nv_bfloat16* VsBuf, int tid)
{
    #pragma unroll
    for (int i = 0; i < 4; i++) {
        const int e  = tid + i * 256;     // 0..1023
        const int r  = e >> 3;            // 0..127
        const int ch = e & 7;
        {
            const int s = r >> 6, rr = r & 63;
            const __nv_bfloat16* ksrc =
                g_kb + (size_t)(b * Tq + k0 + r) * Cq + h * HDq + ch * 8;
            const int sw = (ch ^ (rr & 7)) << 3;
            cpasync16((uint32_t)__cvta_generic_to_shared(&KsBuf[s * 4096 + rr * 64 + sw]), ksrc);
        }
        {
            const int s = r >> 6, d = r & 63;
            const __nv_bfloat16* vsrc =
                g_vT + ((size_t)(b * Hq + h) * HDq + d) * Tq + k0 + s * 64 + ch * 8;
            const int sw = (ch ^ (d & 7)) << 3;
            cpasync16((uint32_t)__cvta_generic_to_shared(&VsBuf[s * 4096 + d * 64 + sw]), vsrc);
        }
    }
}

__global__ __launch_bounds__(256, 2) void fattn_kernel(const float* __restrict__ qkv,
                                                       float* __restrict__ y)
{
    extern __shared__ __nv_bfloat16 smb[];
    __nv_bfloat16* Ks = smb;              // [2][2][64][64]
    __nv_bfloat16* Vs = smb + 2 * KVT;    // [2][2][64][64]

    const int tid  = threadIdx.x;
    const int lane = tid & 31;
    const int w    = tid >> 5;
    const int g    = lane >> 2;
    const int cc   = lane & 3;
    const int b    = blockIdx.z, h = blockIdx.y;
    const int q0   = (int)(gridDim.x - 1 - blockIdx.x) * ATQ;
    const int mrow = w * 16;

    attn_issue_kv(b, h, 0, Ks, Vs, tid);
    asm volatile("cp.async.commit_group;" ::: "memory");

    uint32_t aq[4][4];
    {
        const float* q0p = qkv + (size_t)(b * Tq + q0 + mrow + g) * C3 + h * HDq;
        const float* q1p = q0p + 8 * C3;
        #pragma unroll
        for (int ks = 0; ks < 4; ks++) {
            const int d0 = 16 * ks + 2 * cc;
            float2 x00 = *(const float2*)(q0p + d0);
            float2 x10 = *(const float2*)(q1p + d0);
            float2 x01 = *(const float2*)(q0p + d0 + 8);
            float2 x11 = *(const float2*)(q1p + d0 + 8);
            aq[ks][0] = bf2u(__floats2bfloat162_rn(x00.x * 0.125f, x00.y * 0.125f));
            aq[ks][1] = bf2u(__floats2bfloat162_rn(x10.x * 0.125f, x10.y * 0.125f));
            aq[ks][2] = bf2u(__floats2bfloat162_rn(x01.x * 0.125f, x01.y * 0.125f));
            aq[ks][3] = bf2u(__floats2bfloat162_rn(x11.x * 0.125f, x11.y * 0.125f));
        }
    }

    float of[8][4] = {};
    float m_a = -1e30f, m_b = -1e30f, l_a = 0.0f, l_b = 0.0f;

    const int ntiles = q0 / ATK + 1;
    for (int t = 0; t < ntiles; t++) {
        const int buf = t & 1;
        const bool has_next = (t + 1) < ntiles;
        if (has_next) {
            attn_issue_kv(b, h, (t + 1) * ATK,
                          Ks + (buf ^ 1) * KVT, Vs + (buf ^ 1) * KVT, tid);
            asm volatile("cp.async.commit_group;" ::: "memory");
            asm volatile("cp.async.wait_group 1;" ::: "memory");
        } else {
            asm volatile("cp.async.wait_group 0;" ::: "memory");
        }
        __syncthreads();

        #pragma unroll
        for (int s = 0; s < 2; s++) {
            const int k0s = t * ATK + s * 64;
            if (k0s > q0 + mrow + 15) break;

            const uint32_t* KsW = (const uint32_t*)(Ks + buf * KVT + s * 4096);
            const uint32_t* VsW = (const uint32_t*)(Vs + buf * KVT + s * 4096);

            float sf[8][4] = {};
            #pragma unroll
            for (int ks = 0; ks < 4; ks++) {
                #pragma unroll
                for (int nf = 0; nf < 8; nf++) {
                    const int rk = nf * 8 + g;
                    uint32_t bb[2];
                    bb[0] = KsW[rk * 32 + (((2 * ks    ) ^ g) << 2) + cc];
                    bb[1] = KsW[rk * 32 + (((2 * ks + 1) ^ g) << 2) + cc];
                    mma_bf16(sf[nf], aq[ks], bb);
                }
            }

            if (k0s + 63 > q0 + mrow) {
                const int ta = q0 - k0s + mrow + g;
                const int tb = ta + 8;
                #pragma unroll
                for (int nf = 0; nf < 8; nf++) {
                    const int col0 = nf * 8 + 2 * cc;
                    if (col0     > ta) sf[nf][0] = -1e30f;
                    if (col0 + 1 > ta) sf[nf][1] = -1e30f;
                    if (col0     > tb) sf[nf][2] = -1e30f;
                    if (col0 + 1 > tb) sf[nf][3] = -1e30f;
                }
            }

            float mt_a = -1e30f, mt_b = -1e30f;
            #pragma unroll
            for (int nf = 0; nf < 8; nf++) {
                mt_a = fmaxf(mt_a, fmaxf(sf[nf][0], sf[nf][1]));
                mt_b = fmaxf(mt_b, fmaxf(sf[nf][2], sf[nf][3]));
            }
            mt_a = fmaxf(mt_a, __shfl_xor_sync(0xffffffffu, mt_a, 1));
            mt_a = fmaxf(mt_a, __shfl_xor_sync(0xffffffffu, mt_a, 2));
            mt_b = fmaxf(mt_b, __shfl_xor_sync(0xffffffffu, mt_b, 1));
            mt_b = fmaxf(mt_b, __shfl_xor_sync(0xffffffffu, mt_b, 2));

            const float mn_a = fmaxf(m_a, mt_a), mn_b = fmaxf(m_b, mt_b);
            const float ca = __expf(m_a - mn_a), cb = __expf(m_b - mn_b);
            m_a = mn_a; m_b = mn_b;
            l_a *= ca; l_b *= cb;
            #pragma unroll
            for (int nd = 0; nd < 8; nd++) {
                of[nd][0] *= ca; of[nd][1] *= ca;
                of[nd][2] *= cb; of[nd][3] *= cb;
            }

            uint32_t pa[4][4];
            float sa = 0.0f, sb = 0.0f;
            #pragma unroll
            for (int nf = 0; nf < 8; nf++) {
                const float p0 = __expf(sf[nf][0] - m_a);
                const float p1 = __expf(sf[nf][1] - m_a);
                const float p2 = __expf(sf[nf][2] - m_b);
                const float p3 = __expf(sf[nf][3] - m_b);
                const __nv_bfloat162 hA = __floats2bfloat162_rn(p0, p1);
                const __nv_bfloat162 hB = __floats2bfloat162_rn(p2, p3);
                const float2 rA = __bfloat1622float2(hA);
                const float2 rB = __bfloat1622float2(hB);
                sa += rA.x + rA.y;
                sb += rB.x + rB.y;
                const int ks = nf >> 1;
                if (nf & 1) { pa[ks][2] = bf2u(hA); pa[ks][3] = bf2u(hB); }
                else        { pa[ks][0] = bf2u(hA); pa[ks][1] = bf2u(hB); }
            }
            sa += __shfl_xor_sync(0xffffffffu, sa, 1);
            sa += __shfl_xor_sync(0xffffffffu, sa, 2);
            sb += __shfl_xor_sync(0xffffffffu, sb, 1);
            sb += __shfl_xor_sync(0xffffffffu, sb, 2);
            l_a += sa; l_b += sb;

            #pragma unroll
            for (int ks = 0; ks < 4; ks++) {
                #pragma unroll
                for (int nd = 0; nd < 8; nd++) {
                    const int rv = nd * 8 + g;
                    uint32_t bb[2];
                    bb[0] = VsW[rv * 32 + (((2 * ks    ) ^ g) << 2) + cc];
                    bb[1] = VsW[rv * 32 + (((2 * ks + 1) ^ g) << 2) + cc];
                    mma_bf16(of[nd], pa[ks], bb);
                }
            }
        }
        __syncthreads();
    }

    const float ia = 1.0f / l_a, ib = 1.0f / l_b;
    const int ra = q0 + mrow + g, rb = ra + 8;
    #pragma unroll
    for (int nd = 0; nd < 8; nd++) {
        const int col = h * HDq + nd * 8 + 2 * cc;
        *(float2*)&y[((size_t)(b * Tq) + ra) * Cq + col] =
            make_float2(to_tf32(of[nd][0] * ia), to_tf32(of[nd][1] * ia));
        *(float2*)&y[((size_t)(b * Tq) + rb) * Cq + col] =
            make_float2(to_tf32(of[nd][2] * ib), to_tf32(of[nd][3] * ib));
    }
}

// ---------------- launch ----------------------------------------------------
#define RN1 (Cq*C3/4)
#define RN2 (Cq*Cq/4)
#define RN3 (Cq*C4/4)
#define RN4 (C4*Cq/4)

extern "C" void kernel_launch(void* const* d_in, const int* in_sizes, int n_in,
                              void* d_out, int out_size)
{
    (void)in_sizes; (void)n_in; (void)out_size;
    const float* x           = (const float*)d_in[0];
    const float* ln1_g       = (const float*)d_in[1];
    const float* ln1_b       = (const float*)d_in[2];
    const float* w_attn      = (const float*)d_in[3];
    const float* b_attn      = (const float*)d_in[4];
    const float* w_attn_proj = (const float*)d_in[5];
    const float* b_attn_proj = (const float*)d_in[6];
    const float* ln2_g       = (const float*)d_in[7];
    const float* ln2_b       = (const float*)d_in[8];
    const float* w_fc        = (const float*)d_in[9];
    const float* b_fc        = (const float*)d_in[10];
    const float* w_mlp_proj  = (const float*)d_in[11];
    const float* b_mlp_proj  = (const float*)d_in[12];
    float* out = (float*)d_out;

    float *ln1, *qkv, *att, *x1, *ln2, *fc, *w1, *w2, *w3, *w4;
    cudaGetSymbolAddress((void**)&ln1, g_ln1);
    cudaGetSymbolAddress((void**)&qkv, g_qkv);
    cudaGetSymbolAddress((void**)&att, g_att);
    cudaGetSymbolAddress((void**)&x1,  g_x1);
    cudaGetSymbolAddress((void**)&ln2, g_ln2);
    cudaGetSymbolAddress((void**)&fc,  g_fc);
    cudaGetSymbolAddress((void**)&w1,  g_w_attn);
    cudaGetSymbolAddress((void**)&w2,  g_w_ap);
    cudaGetSymbolAddress((void**)&w3,  g_w_fc);
    cudaGetSymbolAddress((void**)&w4,  g_w_mp);

    cudaFuncSetAttribute(fattn_kernel,
                         cudaFuncAttributeMaxDynamicSharedMemorySize, ATT_SMEM);
    cudaFuncSetAttribute(tgemm_kernel<1>,
                         cudaFuncAttributeMaxDynamicSharedMemorySize, TG_SMEM);
    cudaFuncSetAttribute(tgemm_kernel<2>,
                         cudaFuncAttributeMaxDynamicSharedMemorySize, TG_SMEM);
    cudaFuncSetAttribute(tgemm64_kernel,
                         cudaFuncAttributeMaxDynamicSharedMemorySize, TG64_SMEM);

    // 1-2. weight RNA rounding (two launches so QKV GEMM is launch #4)
    round2_kernel<<<(RN1 + RN2 + 255) / 256, 256>>>(w_attn, w1, RN1, w_attn_proj, w2, RN2);
    round2_kernel<<<(RN3 + RN4 + 255) / 256, 256>>>(w_fc, w3, RN3, w_mlp_proj, w4, RN4);
    // 3. LN1
    ln_kernel<<<Mrows / 8, 256>>>(x, ln1_g, ln1_b, ln1);
    // 4. QKV = ln1 @ w_attn + b_attn  (captured by ncu)
    tgemm_kernel<1><<<dim3(C3 / 128, Mrows / 128), 256, TG_SMEM>>>(ln1, w1, b_attn,
                                                                   nullptr, qkv, Mrows, C3, Cq);
    // 5. pack K/V -> bf16
    pack_kernel<<<KPBLK + VTBLK, 256>>>();
    // 6. bf16 flash attention
    fattn_kernel<<<dim3(Tq / ATQ, Hq, Bq), 256, ATT_SMEM>>>(qkv, att);
    // 7. x1 = x + att @ w_attn_proj + b_attn_proj
    tgemm64_kernel<<<dim3(Cq / 128, Mrows / 64), 256, TG64_SMEM>>>(att, w2, b_attn_proj,
                                                                   x, x1, Mrows, Cq, Cq);
    // 8. LN2
    ln_kernel<<<Mrows / 8, 256>>>(x1, ln2_g, ln2_b, ln2);
    // 9. fc = gelu(ln2 @ w_fc + b_fc)
    tgemm_kernel<2><<<dim3(C4 / 128, Mrows / 128), 256, TG_SMEM>>>(ln2, w3, b_fc,
                                                                   nullptr, fc, Mrows, C4, Cq);
    // 10. out = x1 + fc @ w_mlp_proj + b_mlp_proj
    tgemm64_kernel<<<dim3(Cq / 128, Mrows / 64), 256, TG64_SMEM>>>(fc, w4, b_mlp_proj,
                                                                   x1, out, Mrows, Cq, C4);
}